// round 2
// baseline (speedup 1.0000x reference)
#include <cuda_runtime.h>

#define Bn 2
#define Cn 64
#define CQn 16
#define HWn 9216
#define Dn 96
#define NBLK1 128
#define HWPB1 72      // HWn / NBLK1
#define HWPB3 8
#define NBLK3 1152    // HWn / HWPB3

typedef unsigned long long u64;

// Scratch (no runtime allocation allowed)
__device__ float g_partial[Bn * NBLK1 * Dn * Dn];  // per-block energy partials (~9.4 MB)
__device__ float g_attnT[Bn * Dn * Dn];            // gamma * softmax(energy), stored [b][e][d]

// ---- packed fp32x2 helpers (sm_103a FFMA2) ----
__device__ __forceinline__ u64 pack2(float lo, float hi) {
    u64 r; asm("mov.b64 %0, {%1, %2};" : "=l"(r) : "f"(lo), "f"(hi)); return r;
}
__device__ __forceinline__ u64 splat2(float v) { return pack2(v, v); }
__device__ __forceinline__ void fma2(u64& acc, u64 a, u64 b) {
    asm("fma.rn.f32x2 %0, %1, %2, %0;" : "+l"(acc) : "l"(a), "l"(b));
}
__device__ __forceinline__ u64 lds2(const float* p) { return *reinterpret_cast<const u64*>(p); }

// ============================================================================
// Kernel 1: fused q/k projection + energy partial sums.
// For each hw column X (64 x 96): q = Wq X + bq, k = Wk X + bk (16 x 96 each),
// E += q^T k (96 x 96), accumulated in registers over 72 hw per block.
// ============================================================================
__global__ void __launch_bounds__(256) k_energy(
    const float* __restrict__ x, const float* __restrict__ Wq,
    const float* __restrict__ bq, const float* __restrict__ Wk,
    const float* __restrict__ bk)
{
    __shared__ float Wq_s[CQn * Cn];
    __shared__ float Wk_s[CQn * Cn];
    __shared__ float X_s[Cn][100];   // padded rows (float4-aligned, bank-rotated)
    __shared__ float q_s[CQn][100];
    __shared__ float k_s[CQn][100];

    const int b = blockIdx.y, g = blockIdx.x;
    const int t = threadIdx.x;
    for (int i = t; i < CQn * Cn; i += 256) { Wq_s[i] = Wq[i]; Wk_s[i] = Wk[i]; }

    const int ti = t >> 4, tj = t & 15;
    const int o  = ti;          // q/k output channel this thread computes in stage 1
    const int d0 = tj * 6;      // d-range this thread computes in stage 1
    const float bqv = bq[o], bkv = bk[o];

    u64 E[6][3];                // E tile: rows d = ti*6+i, cols e = tj*6 + 2p + {0,1}
    #pragma unroll
    for (int i = 0; i < 6; i++)
        #pragma unroll
        for (int p = 0; p < 3; p++) E[i][p] = 0ull;

    const float* xb = x + (size_t)b * Cn * HWn * Dn;
    __syncthreads();

    for (int it = 0; it < HWPB1; ++it) {
        const int hw = g * HWPB1 + it;
        // stage X: 64x96 floats, float4-coalesced
        #pragma unroll
        for (int r = 0; r < 6; r++) {
            int idx = t + r * 256;
            int c = idx / 24, d4 = idx % 24;
            *reinterpret_cast<float4*>(&X_s[c][d4 * 4]) =
                *reinterpret_cast<const float4*>(xb + ((size_t)c * HWn + hw) * Dn + d4 * 4);
        }
        __syncthreads();

        // stage 1: q,k rows (each thread: one o, six d, both q and k)
        u64 qa[3], ka[3];
        #pragma unroll
        for (int p = 0; p < 3; p++) { qa[p] = splat2(bqv); ka[p] = splat2(bkv); }
        #pragma unroll 8
        for (int c = 0; c < Cn; c++) {
            u64 wq2 = splat2(Wq_s[o * Cn + c]);
            u64 wk2 = splat2(Wk_s[o * Cn + c]);
            #pragma unroll
            for (int p = 0; p < 3; p++) {
                u64 xp = lds2(&X_s[c][d0 + 2 * p]);
                fma2(qa[p], wq2, xp);
                fma2(ka[p], wk2, xp);
            }
        }
        #pragma unroll
        for (int p = 0; p < 3; p++) {
            *reinterpret_cast<u64*>(&q_s[o][d0 + 2 * p]) = qa[p];
            *reinterpret_cast<u64*>(&k_s[o][d0 + 2 * p]) = ka[p];
        }
        __syncthreads();

        // stage 2: E += q^T k (outer products over 16 o's)
        #pragma unroll 4
        for (int o2 = 0; o2 < CQn; o2++) {
            u64 kp[3];
            #pragma unroll
            for (int p = 0; p < 3; p++) kp[p] = lds2(&k_s[o2][tj * 6 + 2 * p]);
            #pragma unroll
            for (int i = 0; i < 6; i++) {
                u64 q2 = splat2(q_s[o2][ti * 6 + i]);
                #pragma unroll
                for (int p = 0; p < 3; p++) fma2(E[i][p], q2, kp[p]);
            }
        }
        // no sync needed: next X-load touches only X_s; the post-load sync
        // orders it against the next stage-1 q_s/k_s overwrite.
    }

    float* dst = g_partial + ((size_t)(b * NBLK1 + g)) * Dn * Dn;
    #pragma unroll
    for (int i = 0; i < 6; i++)
        #pragma unroll
        for (int p = 0; p < 3; p++)
            *reinterpret_cast<u64*>(&dst[(ti * 6 + i) * Dn + tj * 6 + 2 * p]) = E[i][p];
}

// ============================================================================
// Kernel 2: reduce the 128 partials, softmax over e, fold gamma, store A^T.
// One block per (d, b) row; 96 threads (one per e). Deterministic.
// ============================================================================
__global__ void k_softmax(const float* __restrict__ gamma) {
    const int b = blockIdx.y, d = blockIdx.x;
    const int e = threadIdx.x;
    float v = 0.f;
    for (int g = 0; g < NBLK1; g++)
        v += g_partial[(((size_t)b * NBLK1 + g) * Dn + d) * Dn + e];
    __shared__ float sv[Dn];
    __shared__ float red;
    sv[e] = v;
    __syncthreads();
    if (e == 0) { float m = sv[0]; for (int i = 1; i < Dn; i++) m = fmaxf(m, sv[i]); red = m; }
    __syncthreads();
    float pe = expf(v - red);
    sv[e] = pe;
    __syncthreads();
    if (e == 0) { float s = 0.f; for (int i = 0; i < Dn; i++) s += sv[i]; red = s; }
    __syncthreads();
    g_attnT[((size_t)b * Dn + e) * Dn + d] = gamma[0] * pe / red;  // transposed, gamma folded
}

// ============================================================================
// Kernel 3: fused v projection + attention apply + residual.
// Per hw column: V = Wv X + bv (64x96), out = V A'^T + X, A' = gamma*attn.
// ============================================================================
__global__ void __launch_bounds__(256) k_out(
    const float* __restrict__ x, const float* __restrict__ Wv,
    const float* __restrict__ bv, float* __restrict__ out)
{
    extern __shared__ float sm[];
    float (*X_s)[100] = reinterpret_cast<float(*)[100]>(sm);            // 6400 floats
    float (*V_s)[100] = reinterpret_cast<float(*)[100]>(sm + 6400);     // 6400 floats
    float (*Wv_s)[65] = reinterpret_cast<float(*)[65]>(sm + 12800);     // 4160 floats (pad 65)
    float (*A_s)[Dn]  = reinterpret_cast<float(*)[Dn]>(sm + 16960);     // 9216 floats [e][d]

    const int b = blockIdx.y, g = blockIdx.x, t = threadIdx.x;
    for (int i = t; i < Cn * Cn; i += 256) Wv_s[i >> 6][i & 63] = Wv[i];
    for (int i = t; i < Dn * Dn; i += 256) (&A_s[0][0])[i] = g_attnT[(size_t)b * Dn * Dn + i];

    const int ci = t >> 4, dj = t & 15;
    const int c0 = ci * 4, d0 = dj * 6;       // thread tile: 4 c-rows x 6 d-cols
    float bvv[4];
    #pragma unroll
    for (int i = 0; i < 4; i++) bvv[i] = bv[c0 + i];

    const float* xb = x   + (size_t)b * Cn * HWn * Dn;
    float*       ob = out + (size_t)b * Cn * HWn * Dn;
    __syncthreads();

    for (int it = 0; it < HWPB3; ++it) {
        const int hw = g * HWPB3 + it;
        #pragma unroll
        for (int r = 0; r < 6; r++) {
            int idx = t + r * 256;
            int c = idx / 24, d4 = idx % 24;
            *reinterpret_cast<float4*>(&X_s[c][d4 * 4]) =
                *reinterpret_cast<const float4*>(xb + ((size_t)c * HWn + hw) * Dn + d4 * 4);
        }
        __syncthreads();

        // V = Wv X + bv
        u64 vac[4][3];
        #pragma unroll
        for (int i = 0; i < 4; i++)
            #pragma unroll
            for (int p = 0; p < 3; p++) vac[i][p] = splat2(bvv[i]);
        #pragma unroll 8
        for (int cp = 0; cp < Cn; cp++) {
            u64 xp[3];
            #pragma unroll
            for (int p = 0; p < 3; p++) xp[p] = lds2(&X_s[cp][d0 + 2 * p]);
            #pragma unroll
            for (int i = 0; i < 4; i++) {
                u64 w2 = splat2(Wv_s[c0 + i][cp]);
                #pragma unroll
                for (int p = 0; p < 3; p++) fma2(vac[i][p], w2, xp[p]);
            }
        }
        #pragma unroll
        for (int i = 0; i < 4; i++)
            #pragma unroll
            for (int p = 0; p < 3; p++)
                *reinterpret_cast<u64*>(&V_s[c0 + i][d0 + 2 * p]) = vac[i][p];
        __syncthreads();

        // out = V A'^T + X  (A' already gamma-scaled; residual seeds the acc)
        u64 oac[4][3];
        #pragma unroll
        for (int i = 0; i < 4; i++)
            #pragma unroll
            for (int p = 0; p < 3; p++) oac[i][p] = lds2(&X_s[c0 + i][d0 + 2 * p]);
        #pragma unroll 8
        for (int e = 0; e < Dn; e++) {
            u64 ap[3];
            #pragma unroll
            for (int p = 0; p < 3; p++) ap[p] = lds2(&A_s[e][d0 + 2 * p]);
            #pragma unroll
            for (int i = 0; i < 4; i++) {
                u64 v2 = splat2(V_s[c0 + i][e]);
                #pragma unroll
                for (int p = 0; p < 3; p++) fma2(oac[i][p], v2, ap[p]);
            }
        }
        #pragma unroll
        for (int i = 0; i < 4; i++) {
            float* op = ob + ((size_t)(c0 + i) * HWn + hw) * Dn + d0;
            #pragma unroll
            for (int p = 0; p < 3; p++)
                *reinterpret_cast<u64*>(op + 2 * p) = oac[i][p];
        }
        __syncthreads();   // protect X_s/V_s from next iteration's overwrite
    }
}

extern "C" void kernel_launch(void* const* d_in, const int* in_sizes, int n_in,
                              void* d_out, int out_size) {
    (void)in_sizes; (void)n_in; (void)out_size;
    const float* x     = (const float*)d_in[0];
    const float* Wq    = (const float*)d_in[1];
    const float* bq    = (const float*)d_in[2];
    const float* Wk    = (const float*)d_in[3];
    const float* bk    = (const float*)d_in[4];
    const float* Wv    = (const float*)d_in[5];
    const float* bv    = (const float*)d_in[6];
    const float* gamma = (const float*)d_in[7];
    float* out = (float*)d_out;

    // 104704 B dynamic smem for k_out (X_s + V_s + Wv_s + A_s); 2 blocks/SM.
    cudaFuncSetAttribute(k_out, cudaFuncAttributeMaxDynamicSharedMemorySize, 104704);

    k_energy<<<dim3(NBLK1, Bn), 256>>>(x, Wq, bq, Wk, bk);
    k_softmax<<<dim3(Dn, Bn), Dn>>>(gamma);
    k_out<<<dim3(NBLK3, Bn), 256, 104704>>>(x, Wv, bv, out);
}

// round 4
// speedup vs baseline: 1.3813x; 1.3813x over previous
#include <cuda_runtime.h>
#include <cuda_bf16.h>

#define Bn 2
#define Cn 64
#define CQn 16
#define HWn 9216
#define Dn 96
#define NBLK1 128
#define HWPB1 72      // HWn / NBLK1
#define HWPC 16       // hw columns per CTA in k_out
#define NBLK3 (HWn / HWPC)   // 576

typedef unsigned long long u64;
typedef unsigned int u32;

// Scratch (no runtime allocation allowed)
__device__ float g_partial[Bn * NBLK1 * Dn * Dn];  // per-block energy partials
__device__ float g_attn[Bn * Dn * Dn];             // gamma * softmax(energy), [b][d][e]

// ---- packed fp32x2 helpers (sm_103a FFMA2) ----
__device__ __forceinline__ u64 pack2(float lo, float hi) {
    u64 r; asm("mov.b64 %0, {%1, %2};" : "=l"(r) : "f"(lo), "f"(hi)); return r;
}
__device__ __forceinline__ u64 splat2(float v) { return pack2(v, v); }
__device__ __forceinline__ void fma2(u64& acc, u64 a, u64 b) {
    asm("fma.rn.f32x2 %0, %1, %2, %0;" : "+l"(acc) : "l"(a), "l"(b));
}
__device__ __forceinline__ u64 lds2(const float* p) { return *reinterpret_cast<const u64*>(p); }

// ---- bf16 split helpers ----
__device__ __forceinline__ u32 packbf2(float f0, float f1) {
    // result: low half = bf16(f0), high half = bf16(f1)
    u32 r; asm("cvt.rn.bf16x2.f32 %0, %1, %2;" : "=r"(r) : "f"(f1), "f"(f0)); return r;
}
__device__ __forceinline__ float bflo(u32 p) { return __uint_as_float(p << 16); }
__device__ __forceinline__ float bfhi(u32 p) { return __uint_as_float(p & 0xffff0000u); }

// ---- ldmatrix / mma wrappers ----
__device__ __forceinline__ void ldsm_x4(u32* r, u32 addr) {
    asm volatile("ldmatrix.sync.aligned.m8n8.x4.shared.b16 {%0,%1,%2,%3}, [%4];"
        : "=r"(r[0]), "=r"(r[1]), "=r"(r[2]), "=r"(r[3]) : "r"(addr));
}
__device__ __forceinline__ void ldsm_x2(u32* r, u32 addr) {
    asm volatile("ldmatrix.sync.aligned.m8n8.x2.shared.b16 {%0,%1}, [%2];"
        : "=r"(r[0]), "=r"(r[1]) : "r"(addr));
}
__device__ __forceinline__ void ldsm_x2t(u32* r, u32 addr) {
    asm volatile("ldmatrix.sync.aligned.m8n8.x2.trans.shared.b16 {%0,%1}, [%2];"
        : "=r"(r[0]), "=r"(r[1]) : "r"(addr));
}
__device__ __forceinline__ void mma16816(float* d, const u32* a, const u32* b) {
    asm volatile("mma.sync.aligned.m16n8k16.row.col.f32.bf16.bf16.f32 "
        "{%0,%1,%2,%3}, {%4,%5,%6,%7}, {%8,%9}, {%0,%1,%2,%3};"
        : "+f"(d[0]), "+f"(d[1]), "+f"(d[2]), "+f"(d[3])
        : "r"(a[0]), "r"(a[1]), "r"(a[2]), "r"(a[3]), "r"(b[0]), "r"(b[1]));
}

// ============================================================================
// Kernel 1: fused q/k projection + energy partial sums (fp32 FFMA2, precision-
// critical: softmax logits sigma ~ 384). Unchanged from passing version.
// ============================================================================
__global__ void __launch_bounds__(256) k_energy(
    const float* __restrict__ x, const float* __restrict__ Wq,
    const float* __restrict__ bq, const float* __restrict__ Wk,
    const float* __restrict__ bk)
{
    __shared__ float Wq_s[CQn * Cn];
    __shared__ float Wk_s[CQn * Cn];
    __shared__ float X_s[Cn][100];
    __shared__ float q_s[CQn][100];
    __shared__ float k_s[CQn][100];

    const int b = blockIdx.y, g = blockIdx.x;
    const int t = threadIdx.x;
    for (int i = t; i < CQn * Cn; i += 256) { Wq_s[i] = Wq[i]; Wk_s[i] = Wk[i]; }

    const int ti = t >> 4, tj = t & 15;
    const int o  = ti;
    const int d0 = tj * 6;
    const float bqv = bq[o], bkv = bk[o];

    u64 E[6][3];
    #pragma unroll
    for (int i = 0; i < 6; i++)
        #pragma unroll
        for (int p = 0; p < 3; p++) E[i][p] = 0ull;

    const float* xb = x + (size_t)b * Cn * HWn * Dn;
    __syncthreads();

    for (int it = 0; it < HWPB1; ++it) {
        const int hw = g * HWPB1 + it;
        #pragma unroll
        for (int r = 0; r < 6; r++) {
            int idx = t + r * 256;
            int c = idx / 24, d4 = idx % 24;
            *reinterpret_cast<float4*>(&X_s[c][d4 * 4]) =
                *reinterpret_cast<const float4*>(xb + ((size_t)c * HWn + hw) * Dn + d4 * 4);
        }
        __syncthreads();

        u64 qa[3], ka[3];
        #pragma unroll
        for (int p = 0; p < 3; p++) { qa[p] = splat2(bqv); ka[p] = splat2(bkv); }
        #pragma unroll 8
        for (int c = 0; c < Cn; c++) {
            u64 wq2 = splat2(Wq_s[o * Cn + c]);
            u64 wk2 = splat2(Wk_s[o * Cn + c]);
            #pragma unroll
            for (int p = 0; p < 3; p++) {
                u64 xp = lds2(&X_s[c][d0 + 2 * p]);
                fma2(qa[p], wq2, xp);
                fma2(ka[p], wk2, xp);
            }
        }
        #pragma unroll
        for (int p = 0; p < 3; p++) {
            *reinterpret_cast<u64*>(&q_s[o][d0 + 2 * p]) = qa[p];
            *reinterpret_cast<u64*>(&k_s[o][d0 + 2 * p]) = ka[p];
        }
        __syncthreads();

        #pragma unroll 4
        for (int o2 = 0; o2 < CQn; o2++) {
            u64 kp[3];
            #pragma unroll
            for (int p = 0; p < 3; p++) kp[p] = lds2(&k_s[o2][tj * 6 + 2 * p]);
            #pragma unroll
            for (int i = 0; i < 6; i++) {
                u64 q2 = splat2(q_s[o2][ti * 6 + i]);
                #pragma unroll
                for (int p = 0; p < 3; p++) fma2(E[i][p], q2, kp[p]);
            }
        }
    }

    float* dst = g_partial + ((size_t)(b * NBLK1 + g)) * Dn * Dn;
    #pragma unroll
    for (int i = 0; i < 6; i++)
        #pragma unroll
        for (int p = 0; p < 3; p++)
            *reinterpret_cast<u64*>(&dst[(ti * 6 + i) * Dn + tj * 6 + 2 * p]) = E[i][p];
}

// ============================================================================
// Kernel 2: reduce partials, softmax over e, fold gamma. Stores [b][d][e].
// ============================================================================
__global__ void k_softmax(const float* __restrict__ gamma) {
    const int b = blockIdx.y, d = blockIdx.x;
    const int e = threadIdx.x;
    float v = 0.f;
    for (int g = 0; g < NBLK1; g++)
        v += g_partial[(((size_t)b * NBLK1 + g) * Dn + d) * Dn + e];
    __shared__ float sv[Dn];
    __shared__ float red;
    sv[e] = v;
    __syncthreads();
    if (e == 0) { float m = sv[0]; for (int i = 1; i < Dn; i++) m = fmaxf(m, sv[i]); red = m; }
    __syncthreads();
    float pe = expf(v - red);
    sv[e] = pe;
    __syncthreads();
    if (e == 0) { float s = 0.f; for (int i = 0; i < Dn; i++) s += sv[i]; red = s; }
    __syncthreads();
    g_attn[((size_t)b * Dn + d) * Dn + e] = gamma[0] * pe / red;
}

// ============================================================================
// Kernel 3: fused V projection + attention apply + residual, via split-bf16
// mma.sync (3 MMAs per operand pair: hi*hi + hi*lo + lo*hi, err ~3e-5).
//   GEMM-A: V[c,d] = Wv[c,c'] X[c',d] + bv      (M=64, N=96, K=64)
//   GEMM-B: O[c,d] = V[c,e] A'[d,e] + X[c,d]    (M=64, N=96, K=96)
// X stored c'-major (coalesced), B-fragments via ldmatrix.trans.
// ============================================================================

// smem layout, element offsets in bf16 units (strides padded for conflict-free
// ldmatrix: 72*2=144B (mod128=16), 104*2=208B (mod128=80) — both spread)
#define S_WVH 0                       // Wv hi   [64][72]
#define S_WVL 4608                    // Wv lo
#define S_XH  9216                    // X  hi   [64 c'][104 d]
#define S_XL  15872
#define S_VH  22528                   // V  hi   [64 c][104 e]
#define S_VL  29184
#define S_AH  35840                   // A' hi   [96 d][104 e]
#define S_AL  45824
#define S_TOT 55808                   // *2 = 111616 bytes

__global__ void __launch_bounds__(256, 2) k_out(
    const float* __restrict__ x, const float* __restrict__ Wv,
    const float* __restrict__ bv, float* __restrict__ out)
{
    extern __shared__ __align__(16) u32 smw[];
    __nv_bfloat16* smb = reinterpret_cast<__nv_bfloat16*>(smw);
    const u32 sb = (u32)__cvta_generic_to_shared(smw);

    const int b = blockIdx.y, g = blockIdx.x, t = threadIdx.x;
    const int w = t >> 5, l = t & 31;

    // ---- one-time per CTA: split Wv and A' into hi/lo bf16 ----
    for (int i = t; i < Cn * Cn; i += 256) {
        int c = i >> 6, cc = i & 63;
        float v = Wv[i];
        __nv_bfloat16 h = __float2bfloat16(v);
        smb[S_WVH + c * 72 + cc] = h;
        smb[S_WVL + c * 72 + cc] = __float2bfloat16(v - __bfloat162float(h));
    }
    const float* Ab = g_attn + (size_t)b * Dn * Dn;
    for (int i = t; i < Dn * Dn; i += 256) {
        int d = i / 96, e = i % 96;
        float v = Ab[i];
        __nv_bfloat16 h = __float2bfloat16(v);
        smb[S_AH + d * 104 + e] = h;
        smb[S_AL + d * 104 + e] = __float2bfloat16(v - __bfloat162float(h));
    }

    // warp tiling: mi = c-block (16 rows), nj0 = first of 6 n-tiles (48 d-cols)
    const int mi = w & 3, nj0 = (w >> 2) * 6;
    const int gid = l >> 2, tig = l & 3;
    const float bv0 = bv[16 * mi + gid], bv1 = bv[16 * mi + gid + 8];

    // lane-constant ldmatrix address parts (in elements)
    const int arow  = (l & 7) + (l & 8);          // 0..15 fragment row
    const int acol8 = ((l >> 4) & 1) * 8;         // k-half select
    const int eWa = (16 * mi + arow) * 72 + acol8;    // GEMM-A A (Wv)
    const int eVa = (16 * mi + arow) * 104 + acol8;   // GEMM-B A (V)
    const int xrow = (l & 15);                    // GEMM-A B rows (trans, k = c')
    const int brow = (l & 7);                     // GEMM-B B rows (d)
    const int bcol8 = ((l & 15) >> 3) * 8;        // GEMM-B B k-half

    // X stage mapping: thread -> (c', 24 d-values)
    const int cp = t >> 2;
    const int d0 = (t & 3) * 24;

    const float* xb = x   + (size_t)b * Cn * HWn * Dn;
    float*       ob = out + (size_t)b * Cn * HWn * Dn;

    __syncthreads();

    for (int it = 0; it < HWPC; ++it) {
        const int hw = g * HWPC + it;

        // ---- stage X: load coalesced, split hi/lo, store c'-major ----
        const float4* src = reinterpret_cast<const float4*>(
            xb + ((size_t)cp * HWn + hw) * Dn + d0);
        #pragma unroll
        for (int j = 0; j < 6; j++) {
            float4 f = src[j];
            int e0 = cp * 104 + d0 + 4 * j;
            u32 h0 = packbf2(f.x, f.y), h1 = packbf2(f.z, f.w);
            u32 l0 = packbf2(f.x - bflo(h0), f.y - bfhi(h0));
            u32 l1 = packbf2(f.z - bflo(h1), f.w - bfhi(h1));
            smw[(S_XH + e0) >> 1]       = h0;
            smw[((S_XH + e0) >> 1) + 1] = h1;
            smw[(S_XL + e0) >> 1]       = l0;
            smw[((S_XL + e0) >> 1) + 1] = l1;
        }
        __syncthreads();

        // ---- GEMM-A: acc = Wv * X + bv ----
        float acc[6][4];
        #pragma unroll
        for (int nj = 0; nj < 6; nj++) {
            acc[nj][0] = bv0; acc[nj][1] = bv0; acc[nj][2] = bv1; acc[nj][3] = bv1;
        }
        #pragma unroll
        for (int ks = 0; ks < 4; ks++) {
            u32 ah[4], al[4];
            ldsm_x4(ah, sb + 2u * (S_WVH + eWa + 16 * ks));
            ldsm_x4(al, sb + 2u * (S_WVL + eWa + 16 * ks));
            #pragma unroll
            for (int nj = 0; nj < 6; nj++) {
                u32 bh[2], bl[2];
                u32 be = (16 * ks + xrow) * 104 + 8 * (nj0 + nj);
                ldsm_x2t(bh, sb + 2u * (S_XH + be));
                ldsm_x2t(bl, sb + 2u * (S_XL + be));
                mma16816(acc[nj], ah, bh);
                mma16816(acc[nj], ah, bl);
                mma16816(acc[nj], al, bh);
            }
        }

        // ---- split V to SMEM ----
        #pragma unroll
        for (int nj = 0; nj < 6; nj++) {
            int e  = 8 * (nj0 + nj) + 2 * tig;
            int r0 = 16 * mi + gid, r1 = r0 + 8;
            u32 h0 = packbf2(acc[nj][0], acc[nj][1]);
            u32 p0 = packbf2(acc[nj][0] - bflo(h0), acc[nj][1] - bfhi(h0));
            u32 h1 = packbf2(acc[nj][2], acc[nj][3]);
            u32 p1 = packbf2(acc[nj][2] - bflo(h1), acc[nj][3] - bfhi(h1));
            smw[(S_VH + r0 * 104 + e) >> 1] = h0;
            smw[(S_VL + r0 * 104 + e) >> 1] = p0;
            smw[(S_VH + r1 * 104 + e) >> 1] = h1;
            smw[(S_VL + r1 * 104 + e) >> 1] = p1;
        }
        __syncthreads();

        // ---- GEMM-B: acc = V * A'^T ----
        #pragma unroll
        for (int nj = 0; nj < 6; nj++) {
            acc[nj][0] = 0.f; acc[nj][1] = 0.f; acc[nj][2] = 0.f; acc[nj][3] = 0.f;
        }
        #pragma unroll
        for (int ks = 0; ks < 6; ks++) {
            u32 ah[4], al[4];
            ldsm_x4(ah, sb + 2u * (S_VH + eVa + 16 * ks));
            ldsm_x4(al, sb + 2u * (S_VL + eVa + 16 * ks));
            #pragma unroll
            for (int nj = 0; nj < 6; nj++) {
                u32 bh[2], bl[2];
                u32 be = (8 * (nj0 + nj) + brow) * 104 + 16 * ks + bcol8;
                ldsm_x2(bh, sb + 2u * (S_AH + be));
                ldsm_x2(bl, sb + 2u * (S_AL + be));
                mma16816(acc[nj], ah, bh);
                mma16816(acc[nj], ah, bl);
                mma16816(acc[nj], al, bh);
            }
        }

        // ---- residual (reconstruct X = hi + lo, err ~2^-17) + store ----
        #pragma unroll
        for (int nj = 0; nj < 6; nj++) {
            int d  = 8 * (nj0 + nj) + 2 * tig;
            int r0 = 16 * mi + gid, r1 = r0 + 8;
            u32 xh0 = smw[(S_XH + r0 * 104 + d) >> 1], xl0 = smw[(S_XL + r0 * 104 + d) >> 1];
            u32 xh1 = smw[(S_XH + r1 * 104 + d) >> 1], xl1 = smw[(S_XL + r1 * 104 + d) >> 1];
            float2 o0, o1;
            o0.x = acc[nj][0] + bflo(xh0) + bflo(xl0);
            o0.y = acc[nj][1] + bfhi(xh0) + bfhi(xl0);
            o1.x = acc[nj][2] + bflo(xh1) + bflo(xl1);
            o1.y = acc[nj][3] + bfhi(xh1) + bfhi(xl1);
            *reinterpret_cast<float2*>(ob + ((size_t)r0 * HWn + hw) * Dn + d) = o0;
            *reinterpret_cast<float2*>(ob + ((size_t)r1 * HWn + hw) * Dn + d) = o1;
        }
        __syncthreads();   // protect X/V smem before next iteration's overwrite
    }
}

extern "C" void kernel_launch(void* const* d_in, const int* in_sizes, int n_in,
                              void* d_out, int out_size) {
    (void)in_sizes; (void)n_in; (void)out_size;
    const float* x     = (const float*)d_in[0];
    const float* Wq    = (const float*)d_in[1];
    const float* bq    = (const float*)d_in[2];
    const float* Wk    = (const float*)d_in[3];
    const float* bk    = (const float*)d_in[4];
    const float* Wv    = (const float*)d_in[5];
    const float* bv    = (const float*)d_in[6];
    const float* gamma = (const float*)d_in[7];
    float* out = (float*)d_out;

    cudaFuncSetAttribute(k_out, cudaFuncAttributeMaxDynamicSharedMemorySize,
                         S_TOT * 2);

    k_energy<<<dim3(NBLK1, Bn), 256>>>(x, Wq, bq, Wk, bk);
    k_softmax<<<dim3(Dn, Bn), Dn>>>(gamma);
    k_out<<<dim3(NBLK3, Bn), 256, S_TOT * 2>>>(x, Wv, bv, out);
}

// round 8
// speedup vs baseline: 1.7243x; 1.2483x over previous
#include <cuda_runtime.h>
#include <cuda_bf16.h>
#include <cuda_fp16.h>

#define Bn 2
#define Cn 64
#define CQn 16
#define HWn 9216
#define Dn 96
#define NBLK1 128
#define HWPB1 72      // HWn / NBLK1
#define HWPC 16       // hw columns per CTA in k_out
#define NBLK3 (HWn / HWPC)   // 576

typedef unsigned long long u64;
typedef unsigned int u32;

// Scratch (no runtime allocation allowed)
__device__ float g_partial[Bn * NBLK1 * Dn * Dn];  // per-block energy partials
__device__ float g_attn[Bn * Dn * Dn];             // gamma * softmax(energy), [b][d][e]

// ---- bf16 split helpers (k_out) ----
__device__ __forceinline__ u32 packbf2(float f0, float f1) {
    u32 r; asm("cvt.rn.bf16x2.f32 %0, %1, %2;" : "=r"(r) : "f"(f1), "f"(f0)); return r;
}
__device__ __forceinline__ float bflo(u32 p) { return __uint_as_float(p << 16); }
__device__ __forceinline__ float bfhi(u32 p) { return __uint_as_float(p & 0xffff0000u); }

// ---- fp16 split helpers (k_energy) ----
__device__ __forceinline__ u32 packhf2(float f0, float f1) {
    u32 r; asm("cvt.rn.f16x2.f32 %0, %1, %2;" : "=r"(r) : "f"(f1), "f"(f0)); return r;
}
__device__ __forceinline__ float hflo(u32 p) {
    return __half2float(__ushort_as_half((unsigned short)(p & 0xffffu)));
}
__device__ __forceinline__ float hfhi(u32 p) {
    return __half2float(__ushort_as_half((unsigned short)(p >> 16)));
}

// ---- ldmatrix / mma wrappers ----
__device__ __forceinline__ void ldsm_x4(u32* r, u32 addr) {
    asm volatile("ldmatrix.sync.aligned.m8n8.x4.shared.b16 {%0,%1,%2,%3}, [%4];"
        : "=r"(r[0]), "=r"(r[1]), "=r"(r[2]), "=r"(r[3]) : "r"(addr));
}
__device__ __forceinline__ void ldsm_x2(u32* r, u32 addr) {
    asm volatile("ldmatrix.sync.aligned.m8n8.x2.shared.b16 {%0,%1}, [%2];"
        : "=r"(r[0]), "=r"(r[1]) : "r"(addr));
}
__device__ __forceinline__ void ldsm_x2t(u32* r, u32 addr) {
    asm volatile("ldmatrix.sync.aligned.m8n8.x2.trans.shared.b16 {%0,%1}, [%2];"
        : "=r"(r[0]), "=r"(r[1]) : "r"(addr));
}
__device__ __forceinline__ void mma_bf(float* d, const u32* a, const u32* b) {
    asm volatile("mma.sync.aligned.m16n8k16.row.col.f32.bf16.bf16.f32 "
        "{%0,%1,%2,%3}, {%4,%5,%6,%7}, {%8,%9}, {%0,%1,%2,%3};"
        : "+f"(d[0]), "+f"(d[1]), "+f"(d[2]), "+f"(d[3])
        : "r"(a[0]), "r"(a[1]), "r"(a[2]), "r"(a[3]), "r"(b[0]), "r"(b[1]));
}
__device__ __forceinline__ void mma_hf(float* d, const u32* a, const u32* b) {
    asm volatile("mma.sync.aligned.m16n8k16.row.col.f32.f16.f16.f32 "
        "{%0,%1,%2,%3}, {%4,%5,%6,%7}, {%8,%9}, {%0,%1,%2,%3};"
        : "+f"(d[0]), "+f"(d[1]), "+f"(d[2]), "+f"(d[3])
        : "r"(a[0]), "r"(a[1]), "r"(a[2]), "r"(a[3]), "r"(b[0]), "r"(b[1]));
}

// ============================================================================
// Kernel 1 (MMA version): fused q/k projection + energy, split-fp16 (3 MMAs
// per product pair; per-term rel err ~7e-7 -> logit abs err ~3e-4: safe).
//   proj:   q[o,d] = Wq[o,c] X[c,d] + bq   (M=16, N=96, K=64)  (k likewise)
//   energy: E[d,e] += sum_o q[o,d] k[o,e]  (M=96, N=96, K=16)
// q,k written TRANSPOSED ([d][o], stride 24: conflict-free ldmatrix) so the
// energy MMA reads both operands without trans.
// ============================================================================

// smem offsets in fp16 elements
#define E_WQH 0                       // Wq hi [16][72]
#define E_WQL 1152
#define E_WKH 2304
#define E_WKL 3456
#define E_XH  4608                    // X  hi [64 c][104 d]
#define E_XL  11264
#define E_QTH 17920                   // qT hi [96 d][24 o]
#define E_QTL 20224
#define E_KTH 22528                   // kT hi [96 e][24 o]
#define E_KTL 24832
#define E_TOT 27136                   // *2 = 54272 bytes

__global__ void __launch_bounds__(256, 2) k_energy(
    const float* __restrict__ x, const float* __restrict__ Wq,
    const float* __restrict__ bq, const float* __restrict__ Wk,
    const float* __restrict__ bk)
{
    extern __shared__ __align__(16) u32 smw[];
    __half* smh = reinterpret_cast<__half*>(smw);
    const u32 sb = (u32)__cvta_generic_to_shared(smw);

    const int b = blockIdx.y, g = blockIdx.x, t = threadIdx.x;
    const int w = t >> 5, l = t & 31;

    // one-time: split Wq, Wk into hi/lo fp16
    for (int i = t; i < CQn * Cn; i += 256) {
        int o = i >> 6, c = i & 63;
        float vq = Wq[i], vk = Wk[i];
        __half hq = __float2half_rn(vq), hk = __float2half_rn(vk);
        smh[E_WQH + o * 72 + c] = hq;
        smh[E_WQL + o * 72 + c] = __float2half_rn(vq - __half2float(hq));
        smh[E_WKH + o * 72 + c] = hk;
        smh[E_WKL + o * 72 + c] = __float2half_rn(vk - __half2float(hk));
    }

    // projection role: warps 0-3 -> q, 4-7 -> k; each covers 3 n-tiles (24 d)
    const int qk  = w >> 2;
    const int nb  = (w & 3) * 3;
    const int gid = l >> 2, tig = l & 3;
    const int waH = qk ? E_WKH : E_WQH;
    const int waL = qk ? E_WKL : E_WQL;
    const int tH  = qk ? E_KTH : E_QTH;
    const int tL  = qk ? E_KTL : E_QTL;
    const float* bias = qk ? bk : bq;
    const float bs0 = bias[gid], bs1 = bias[gid + 8];

    // lane-constant ldmatrix address parts (fp16-element units)
    const int arow  = (l & 7) + (l & 8);
    const int acol8 = ((l >> 4) & 1) * 8;
    const int xrow  = (l & 15);
    const int brow  = (l & 7);
    const int bcol8 = ((l & 15) >> 3) * 8;

    // energy tiling: warp w -> m-tiles 3*(w>>2)+{0,1,2}, n-tiles 3*(w&3)+{0,1,2}
    const int mw = w >> 2, nwq = w & 3;

    float E[3][3][4];
    #pragma unroll
    for (int im = 0; im < 3; im++)
        #pragma unroll
        for (int in = 0; in < 3; in++)
            #pragma unroll
            for (int p = 0; p < 4; p++) E[im][in][p] = 0.f;

    // X stage mapping: thread -> (c, 24 d-values)
    const int cp = t >> 2;
    const int d0 = (t & 3) * 24;
    const float* xb = x + (size_t)b * Cn * HWn * Dn;

    __syncthreads();

    for (int it = 0; it < HWPB1; ++it) {
        const int hw = g * HWPB1 + it;

        // ---- stage X: coalesced load, split hi/lo fp16, store [c][d] ----
        const float4* src = reinterpret_cast<const float4*>(
            xb + ((size_t)cp * HWn + hw) * Dn + d0);
        #pragma unroll
        for (int j = 0; j < 6; j++) {
            float4 f = src[j];
            int e0 = cp * 104 + d0 + 4 * j;
            u32 h0 = packhf2(f.x, f.y), h1 = packhf2(f.z, f.w);
            u32 l0 = packhf2(f.x - hflo(h0), f.y - hfhi(h0));
            u32 l1 = packhf2(f.z - hflo(h1), f.w - hfhi(h1));
            smw[(E_XH + e0) >> 1]       = h0;
            smw[((E_XH + e0) >> 1) + 1] = h1;
            smw[(E_XL + e0) >> 1]       = l0;
            smw[((E_XL + e0) >> 1) + 1] = l1;
        }
        __syncthreads();

        // ---- projection: acc = W * X + bias (this warp's 3 n-tiles) ----
        float acc[3][4];
        #pragma unroll
        for (int nj = 0; nj < 3; nj++) {
            acc[nj][0] = bs0; acc[nj][1] = bs0; acc[nj][2] = bs1; acc[nj][3] = bs1;
        }
        #pragma unroll
        for (int ks = 0; ks < 4; ks++) {
            u32 ah[4], al[4];
            ldsm_x4(ah, sb + 2u * (waH + arow * 72 + acol8 + 16 * ks));
            ldsm_x4(al, sb + 2u * (waL + arow * 72 + acol8 + 16 * ks));
            #pragma unroll
            for (int nj = 0; nj < 3; nj++) {
                u32 bh[2], bl[2];
                u32 be = (16 * ks + xrow) * 104 + 8 * (nb + nj);
                ldsm_x2t(bh, sb + 2u * (E_XH + be));
                ldsm_x2t(bl, sb + 2u * (E_XL + be));
                mma_hf(acc[nj], ah, bh);
                mma_hf(acc[nj], ah, bl);
                mma_hf(acc[nj], al, bh);
            }
        }

        // ---- write q/k transposed, split hi/lo: [d][o] stride 24 ----
        #pragma unroll
        for (int nj = 0; nj < 3; nj++) {
            int dc = 8 * (nb + nj) + 2 * tig;
            #pragma unroll
            for (int p = 0; p < 4; p++) {
                int dd = dc + (p & 1);
                int oo = gid + (p >> 1) * 8;
                float v = acc[nj][p];
                __half h = __float2half_rn(v);
                smh[tH + dd * 24 + oo] = h;
                smh[tL + dd * 24 + oo] = __float2half_rn(v - __half2float(h));
            }
        }
        __syncthreads();

        // ---- energy: E += qT * kT^T   (M=96, N=96, K=16: one k-step) ----
        #pragma unroll
        for (int im = 0; im < 3; im++) {
            u32 ah[4], al[4];
            u32 ae = (16 * (3 * mw + im) + arow) * 24 + acol8;
            ldsm_x4(ah, sb + 2u * (E_QTH + ae));
            ldsm_x4(al, sb + 2u * (E_QTL + ae));
            #pragma unroll
            for (int in = 0; in < 3; in++) {
                u32 bh[2], bl[2];
                u32 be = (8 * (3 * nwq + in) + brow) * 24 + bcol8;
                ldsm_x2(bh, sb + 2u * (E_KTH + be));
                ldsm_x2(bl, sb + 2u * (E_KTL + be));
                mma_hf(E[im][in], ah, bh);
                mma_hf(E[im][in], ah, bl);
                mma_hf(E[im][in], al, bh);
            }
        }
        // next X-load touches only XH/XL (disjoint from qT/kT); the sync after
        // it orders energy reads against the next projection's qT/kT writes.
    }

    // ---- write E partials ----
    float* dst = g_partial + ((size_t)(b * NBLK1 + g)) * Dn * Dn;
    #pragma unroll
    for (int im = 0; im < 3; im++)
        #pragma unroll
        for (int in = 0; in < 3; in++) {
            int r = 16 * (3 * mw + im) + gid;
            int c = 8 * (3 * nwq + in) + 2 * tig;
            *reinterpret_cast<float2*>(&dst[(size_t)r * Dn + c]) =
                make_float2(E[im][in][0], E[im][in][1]);
            *reinterpret_cast<float2*>(&dst[(size_t)(r + 8) * Dn + c]) =
                make_float2(E[im][in][2], E[im][in][3]);
        }
}

// ============================================================================
// Kernel 2: reduce partials, softmax over e, fold gamma. Stores [b][d][e].
// ============================================================================
__global__ void k_softmax(const float* __restrict__ gamma) {
    const int b = blockIdx.y, d = blockIdx.x;
    const int e = threadIdx.x;
    float v = 0.f;
    for (int g = 0; g < NBLK1; g++)
        v += g_partial[(((size_t)b * NBLK1 + g) * Dn + d) * Dn + e];
    __shared__ float sv[Dn];
    __shared__ float red;
    sv[e] = v;
    __syncthreads();
    if (e == 0) { float m = sv[0]; for (int i = 1; i < Dn; i++) m = fmaxf(m, sv[i]); red = m; }
    __syncthreads();
    float pe = expf(v - red);
    sv[e] = pe;
    __syncthreads();
    if (e == 0) { float s = 0.f; for (int i = 0; i < Dn; i++) s += sv[i]; red = s; }
    __syncthreads();
    g_attn[((size_t)b * Dn + d) * Dn + e] = gamma[0] * pe / red;
}

// ============================================================================
// Kernel 3: fused V projection + attention apply + residual (split-bf16 MMA).
// Unchanged from the passing 903us version.
// ============================================================================
#define S_WVH 0
#define S_WVL 4608
#define S_XH  9216
#define S_XL  15872
#define S_VH  22528
#define S_VL  29184
#define S_AH  35840
#define S_AL  45824
#define S_TOT 55808

__global__ void __launch_bounds__(256, 2) k_out(
    const float* __restrict__ x, const float* __restrict__ Wv,
    const float* __restrict__ bv, float* __restrict__ out)
{
    extern __shared__ __align__(16) u32 smw[];
    __nv_bfloat16* smb = reinterpret_cast<__nv_bfloat16*>(smw);
    const u32 sb = (u32)__cvta_generic_to_shared(smw);

    const int b = blockIdx.y, g = blockIdx.x, t = threadIdx.x;
    const int w = t >> 5, l = t & 31;

    for (int i = t; i < Cn * Cn; i += 256) {
        int c = i >> 6, cc = i & 63;
        float v = Wv[i];
        __nv_bfloat16 h = __float2bfloat16(v);
        smb[S_WVH + c * 72 + cc] = h;
        smb[S_WVL + c * 72 + cc] = __float2bfloat16(v - __bfloat162float(h));
    }
    const float* Ab = g_attn + (size_t)b * Dn * Dn;
    for (int i = t; i < Dn * Dn; i += 256) {
        int d = i / 96, e = i % 96;
        float v = Ab[i];
        __nv_bfloat16 h = __float2bfloat16(v);
        smb[S_AH + d * 104 + e] = h;
        smb[S_AL + d * 104 + e] = __float2bfloat16(v - __bfloat162float(h));
    }

    const int mi = w & 3, nj0 = (w >> 2) * 6;
    const int gid = l >> 2, tig = l & 3;
    const float bv0 = bv[16 * mi + gid], bv1 = bv[16 * mi + gid + 8];

    const int arow  = (l & 7) + (l & 8);
    const int acol8 = ((l >> 4) & 1) * 8;
    const int eWa = (16 * mi + arow) * 72 + acol8;
    const int eVa = (16 * mi + arow) * 104 + acol8;
    const int xrow = (l & 15);
    const int brow = (l & 7);
    const int bcol8 = ((l & 15) >> 3) * 8;

    const int cp = t >> 2;
    const int d0 = (t & 3) * 24;

    const float* xb = x   + (size_t)b * Cn * HWn * Dn;
    float*       ob = out + (size_t)b * Cn * HWn * Dn;

    __syncthreads();

    for (int it = 0; it < HWPC; ++it) {
        const int hw = g * HWPC + it;

        const float4* src = reinterpret_cast<const float4*>(
            xb + ((size_t)cp * HWn + hw) * Dn + d0);
        #pragma unroll
        for (int j = 0; j < 6; j++) {
            float4 f = src[j];
            int e0 = cp * 104 + d0 + 4 * j;
            u32 h0 = packbf2(f.x, f.y), h1 = packbf2(f.z, f.w);
            u32 l0 = packbf2(f.x - bflo(h0), f.y - bfhi(h0));
            u32 l1 = packbf2(f.z - bflo(h1), f.w - bfhi(h1));
            smw[(S_XH + e0) >> 1]       = h0;
            smw[((S_XH + e0) >> 1) + 1] = h1;
            smw[(S_XL + e0) >> 1]       = l0;
            smw[((S_XL + e0) >> 1) + 1] = l1;
        }
        __syncthreads();

        float acc[6][4];
        #pragma unroll
        for (int nj = 0; nj < 6; nj++) {
            acc[nj][0] = bv0; acc[nj][1] = bv0; acc[nj][2] = bv1; acc[nj][3] = bv1;
        }
        #pragma unroll
        for (int ks = 0; ks < 4; ks++) {
            u32 ah[4], al[4];
            ldsm_x4(ah, sb + 2u * (S_WVH + eWa + 16 * ks));
            ldsm_x4(al, sb + 2u * (S_WVL + eWa + 16 * ks));
            #pragma unroll
            for (int nj = 0; nj < 6; nj++) {
                u32 bh[2], bl[2];
                u32 be = (16 * ks + xrow) * 104 + 8 * (nj0 + nj);
                ldsm_x2t(bh, sb + 2u * (S_XH + be));
                ldsm_x2t(bl, sb + 2u * (S_XL + be));
                mma_bf(acc[nj], ah, bh);
                mma_bf(acc[nj], ah, bl);
                mma_bf(acc[nj], al, bh);
            }
        }

        #pragma unroll
        for (int nj = 0; nj < 6; nj++) {
            int e  = 8 * (nj0 + nj) + 2 * tig;
            int r0 = 16 * mi + gid, r1 = r0 + 8;
            u32 h0 = packbf2(acc[nj][0], acc[nj][1]);
            u32 p0 = packbf2(acc[nj][0] - bflo(h0), acc[nj][1] - bfhi(h0));
            u32 h1 = packbf2(acc[nj][2], acc[nj][3]);
            u32 p1 = packbf2(acc[nj][2] - bflo(h1), acc[nj][3] - bfhi(h1));
            smw[(S_VH + r0 * 104 + e) >> 1] = h0;
            smw[(S_VL + r0 * 104 + e) >> 1] = p0;
            smw[(S_VH + r1 * 104 + e) >> 1] = h1;
            smw[(S_VL + r1 * 104 + e) >> 1] = p1;
        }
        __syncthreads();

        #pragma unroll
        for (int nj = 0; nj < 6; nj++) {
            acc[nj][0] = 0.f; acc[nj][1] = 0.f; acc[nj][2] = 0.f; acc[nj][3] = 0.f;
        }
        #pragma unroll
        for (int ks = 0; ks < 6; ks++) {
            u32 ah[4], al[4];
            ldsm_x4(ah, sb + 2u * (S_VH + eVa + 16 * ks));
            ldsm_x4(al, sb + 2u * (S_VL + eVa + 16 * ks));
            #pragma unroll
            for (int nj = 0; nj < 6; nj++) {
                u32 bh[2], bl[2];
                u32 be = (8 * (nj0 + nj) + brow) * 104 + 16 * ks + bcol8;
                ldsm_x2(bh, sb + 2u * (S_AH + be));
                ldsm_x2(bl, sb + 2u * (S_AL + be));
                mma_bf(acc[nj], ah, bh);
                mma_bf(acc[nj], ah, bl);
                mma_bf(acc[nj], al, bh);
            }
        }

        #pragma unroll
        for (int nj = 0; nj < 6; nj++) {
            int d  = 8 * (nj0 + nj) + 2 * tig;
            int r0 = 16 * mi + gid, r1 = r0 + 8;
            u32 xh0 = smw[(S_XH + r0 * 104 + d) >> 1], xl0 = smw[(S_XL + r0 * 104 + d) >> 1];
            u32 xh1 = smw[(S_XH + r1 * 104 + d) >> 1], xl1 = smw[(S_XL + r1 * 104 + d) >> 1];
            float2 o0, o1;
            o0.x = acc[nj][0] + bflo(xh0) + bflo(xl0);
            o0.y = acc[nj][1] + bfhi(xh0) + bfhi(xl0);
            o1.x = acc[nj][2] + bflo(xh1) + bflo(xl1);
            o1.y = acc[nj][3] + bfhi(xh1) + bfhi(xl1);
            *reinterpret_cast<float2*>(ob + ((size_t)r0 * HWn + hw) * Dn + d) = o0;
            *reinterpret_cast<float2*>(ob + ((size_t)r1 * HWn + hw) * Dn + d) = o1;
        }
        __syncthreads();
    }
}

extern "C" void kernel_launch(void* const* d_in, const int* in_sizes, int n_in,
                              void* d_out, int out_size) {
    (void)in_sizes; (void)n_in; (void)out_size;
    const float* x     = (const float*)d_in[0];
    const float* Wq    = (const float*)d_in[1];
    const float* bq    = (const float*)d_in[2];
    const float* Wk    = (const float*)d_in[3];
    const float* bk    = (const float*)d_in[4];
    const float* Wv    = (const float*)d_in[5];
    const float* bv    = (const float*)d_in[6];
    const float* gamma = (const float*)d_in[7];
    float* out = (float*)d_out;

    cudaFuncSetAttribute(k_energy, cudaFuncAttributeMaxDynamicSharedMemorySize, E_TOT * 2);
    cudaFuncSetAttribute(k_out,    cudaFuncAttributeMaxDynamicSharedMemorySize, S_TOT * 2);

    k_energy<<<dim3(NBLK1, Bn), 256, E_TOT * 2>>>(x, Wq, bq, Wk, bk);
    k_softmax<<<dim3(Dn, Bn), Dn>>>(gamma);
    k_out<<<dim3(NBLK3, Bn), 256, S_TOT * 2>>>(x, Wv, bv, out);
}

// round 11
// speedup vs baseline: 1.9382x; 1.1240x over previous
#include <cuda_runtime.h>
#include <cuda_bf16.h>
#include <cuda_fp16.h>

#define Bn 2
#define Cn 64
#define CQn 16
#define HWn 9216
#define Dn 96
#define NBLK1 128
#define HWPB1 72      // HWn / NBLK1
#define HWPC 16       // hw columns per CTA in k_out
#define NBLK3 (HWn / HWPC)   // 576

typedef unsigned long long u64;
typedef unsigned int u32;

// Scratch (no runtime allocation allowed)
__device__ float g_partial[Bn * NBLK1 * Dn * Dn];  // per-block energy partials
__device__ float g_attn[Bn * Dn * Dn];             // gamma * softmax(energy), [b][d][e]

// ---- bf16 split helpers (k_out) ----
__device__ __forceinline__ u32 packbf2(float f0, float f1) {
    u32 r; asm("cvt.rn.bf16x2.f32 %0, %1, %2;" : "=r"(r) : "f"(f1), "f"(f0)); return r;
}
__device__ __forceinline__ float bflo(u32 p) { return __uint_as_float(p << 16); }
__device__ __forceinline__ float bfhi(u32 p) { return __uint_as_float(p & 0xffff0000u); }

// ---- fp16 split helpers (k_energy) ----
__device__ __forceinline__ u32 packhf2(float f0, float f1) {
    u32 r; asm("cvt.rn.f16x2.f32 %0, %1, %2;" : "=r"(r) : "f"(f1), "f"(f0)); return r;
}
__device__ __forceinline__ float hflo(u32 p) {
    return __half2float(__ushort_as_half((unsigned short)(p & 0xffffu)));
}
__device__ __forceinline__ float hfhi(u32 p) {
    return __half2float(__ushort_as_half((unsigned short)(p >> 16)));
}

// ---- ldmatrix / mma wrappers ----
__device__ __forceinline__ void ldsm_x4(u32* r, u32 addr) {
    asm volatile("ldmatrix.sync.aligned.m8n8.x4.shared.b16 {%0,%1,%2,%3}, [%4];"
        : "=r"(r[0]), "=r"(r[1]), "=r"(r[2]), "=r"(r[3]) : "r"(addr));
}
__device__ __forceinline__ void ldsm_x4t(u32* r, u32 addr) {
    asm volatile("ldmatrix.sync.aligned.m8n8.x4.trans.shared.b16 {%0,%1,%2,%3}, [%4];"
        : "=r"(r[0]), "=r"(r[1]), "=r"(r[2]), "=r"(r[3]) : "r"(addr));
}
__device__ __forceinline__ void ldsm_x2(u32* r, u32 addr) {
    asm volatile("ldmatrix.sync.aligned.m8n8.x2.shared.b16 {%0,%1}, [%2];"
        : "=r"(r[0]), "=r"(r[1]) : "r"(addr));
}
__device__ __forceinline__ void ldsm_x2t(u32* r, u32 addr) {
    asm volatile("ldmatrix.sync.aligned.m8n8.x2.trans.shared.b16 {%0,%1}, [%2];"
        : "=r"(r[0]), "=r"(r[1]) : "r"(addr));
}
__device__ __forceinline__ void mma_bf(float* d, const u32* a, const u32* b) {
    asm volatile("mma.sync.aligned.m16n8k16.row.col.f32.bf16.bf16.f32 "
        "{%0,%1,%2,%3}, {%4,%5,%6,%7}, {%8,%9}, {%0,%1,%2,%3};"
        : "+f"(d[0]), "+f"(d[1]), "+f"(d[2]), "+f"(d[3])
        : "r"(a[0]), "r"(a[1]), "r"(a[2]), "r"(a[3]), "r"(b[0]), "r"(b[1]));
}
__device__ __forceinline__ void mma_hf(float* d, const u32* a, const u32* b) {
    asm volatile("mma.sync.aligned.m16n8k16.row.col.f32.f16.f16.f32 "
        "{%0,%1,%2,%3}, {%4,%5,%6,%7}, {%8,%9}, {%0,%1,%2,%3};"
        : "+f"(d[0]), "+f"(d[1]), "+f"(d[2]), "+f"(d[3])
        : "r"(a[0]), "r"(a[1]), "r"(a[2]), "r"(a[3]), "r"(b[0]), "r"(b[1]));
}
__device__ __forceinline__ u64 mk64(u32 lo, u32 hi) {
    return (u64)lo | ((u64)hi << 32);
}

// ============================================================================
// Kernel 1: fused q/k projection + energy, split-fp16 MMA.
// x4-paired B ldmatrix, hoisted energy B-frags, register-prefetch of next
// X column, 64-bit staging stores.
// ============================================================================

#define E_WQH 0                       // Wq hi [16][72]
#define E_WQL 1152
#define E_WKH 2304
#define E_WKL 3456
#define E_XH  4608                    // X  hi [64 c][104 d]
#define E_XL  11264
#define E_QTH 17920                   // qT hi [96 d][24 o]
#define E_QTL 20224
#define E_KTH 22528                   // kT hi [96 e][24 o]
#define E_KTL 24832
#define E_TOT 27136                   // *2 = 54272 bytes

__global__ void __launch_bounds__(256, 2) k_energy(
    const float* __restrict__ x, const float* __restrict__ Wq,
    const float* __restrict__ bq, const float* __restrict__ Wk,
    const float* __restrict__ bk)
{
    extern __shared__ __align__(16) u32 smw[];
    __half* smh = reinterpret_cast<__half*>(smw);
    u64* smq = reinterpret_cast<u64*>(smw);
    const u32 sb = (u32)__cvta_generic_to_shared(smw);

    const int b = blockIdx.y, g = blockIdx.x, t = threadIdx.x;
    const int w = t >> 5, l = t & 31;

    // one-time: split Wq, Wk into hi/lo fp16
    for (int i = t; i < CQn * Cn; i += 256) {
        int o = i >> 6, c = i & 63;
        float vq = Wq[i], vk = Wk[i];
        __half hq = __float2half_rn(vq), hk = __float2half_rn(vk);
        smh[E_WQH + o * 72 + c] = hq;
        smh[E_WQL + o * 72 + c] = __float2half_rn(vq - __half2float(hq));
        smh[E_WKH + o * 72 + c] = hk;
        smh[E_WKL + o * 72 + c] = __float2half_rn(vk - __half2float(hk));
    }

    const int qk  = w >> 2;
    const int nb  = (w & 3) * 3;
    const int gid = l >> 2, tig = l & 3;
    const int waH = qk ? E_WKH : E_WQH;
    const int waL = qk ? E_WKL : E_WQL;
    const int tH  = qk ? E_KTH : E_QTH;
    const int tL  = qk ? E_KTL : E_QTL;
    const float* bias = qk ? bk : bq;
    const float bs0 = bias[gid], bs1 = bias[gid + 8];

    // lane-constant ldmatrix address parts
    const int arow  = (l & 7) + (l & 8);
    const int acol8 = ((l >> 4) & 1) * 8;
    const int xrow  = (l & 15);
    const int brow  = (l & 7);
    const int bcol8 = ((l & 15) >> 3) * 8;
    const int pl    = (l >> 4) & 1;           // pair-tile select for x4 loads
    const int prow  = (l & 7);
    const int pcol8 = ((l >> 3) & 1) * 8;

    const int mw = w >> 2, nwq = w & 3;

    float E[3][3][4];
    #pragma unroll
    for (int im = 0; im < 3; im++)
        #pragma unroll
        for (int in = 0; in < 3; in++)
            #pragma unroll
            for (int p = 0; p < 4; p++) E[im][in][p] = 0.f;

    const int cp = t >> 2;
    const int d0 = (t & 3) * 24;
    const float* xb = x + (size_t)b * Cn * HWn * Dn;

    // prefetch X column 0
    float4 xf[6];
    {
        const float4* src = reinterpret_cast<const float4*>(
            xb + ((size_t)cp * HWn + (size_t)g * HWPB1) * Dn + d0);
        #pragma unroll
        for (int j = 0; j < 6; j++) xf[j] = src[j];
    }

    __syncthreads();

    for (int it = 0; it < HWPB1; ++it) {
        // ---- stage X from prefetched regs: split hi/lo fp16, 64-bit stores ----
        #pragma unroll
        for (int j = 0; j < 6; j++) {
            float4 f = xf[j];
            int e0 = cp * 104 + d0 + 4 * j;
            u32 h0 = packhf2(f.x, f.y), h1 = packhf2(f.z, f.w);
            u32 l0 = packhf2(f.x - hflo(h0), f.y - hfhi(h0));
            u32 l1 = packhf2(f.z - hflo(h1), f.w - hfhi(h1));
            smq[(E_XH + e0) >> 2] = mk64(h0, h1);
            smq[(E_XL + e0) >> 2] = mk64(l0, l1);
        }
        __syncthreads();

        // issue next column's LDGs; consumed next iteration (hides DRAM lat)
        if (it + 1 < HWPB1) {
            const float4* src = reinterpret_cast<const float4*>(
                xb + ((size_t)cp * HWn + (size_t)(g * HWPB1 + it + 1)) * Dn + d0);
            #pragma unroll
            for (int j = 0; j < 6; j++) xf[j] = src[j];
        }

        // ---- projection: acc = W * X + bias (3 n-tiles; B x4-paired) ----
        float acc[3][4];
        #pragma unroll
        for (int nj = 0; nj < 3; nj++) {
            acc[nj][0] = bs0; acc[nj][1] = bs0; acc[nj][2] = bs1; acc[nj][3] = bs1;
        }
        #pragma unroll
        for (int ks = 0; ks < 4; ks++) {
            u32 ah[4], al[4];
            ldsm_x4(ah, sb + 2u * (waH + arow * 72 + acol8 + 16 * ks));
            ldsm_x4(al, sb + 2u * (waL + arow * 72 + acol8 + 16 * ks));
            // n-tiles nb, nb+1 via one x4.trans pair each for hi and lo
            u32 rh[4], rl[4];
            u32 beP = (16 * ks + xrow) * 104 + 8 * (nb + pl);
            ldsm_x4t(rh, sb + 2u * (E_XH + beP));
            ldsm_x4t(rl, sb + 2u * (E_XL + beP));
            mma_hf(acc[0], ah, rh);     mma_hf(acc[0], ah, rl);     mma_hf(acc[0], al, rh);
            mma_hf(acc[1], ah, rh + 2); mma_hf(acc[1], ah, rl + 2); mma_hf(acc[1], al, rh + 2);
            // n-tile nb+2 via x2.trans
            u32 bh2[2], bl2[2];
            u32 be2 = (16 * ks + xrow) * 104 + 8 * (nb + 2);
            ldsm_x2t(bh2, sb + 2u * (E_XH + be2));
            ldsm_x2t(bl2, sb + 2u * (E_XL + be2));
            mma_hf(acc[2], ah, bh2); mma_hf(acc[2], ah, bl2); mma_hf(acc[2], al, bh2);
        }

        // ---- write q/k transposed, split hi/lo: [d][o] stride 24 ----
        #pragma unroll
        for (int nj = 0; nj < 3; nj++) {
            int dc = 8 * (nb + nj) + 2 * tig;
            #pragma unroll
            for (int p = 0; p < 4; p++) {
                int dd = dc + (p & 1);
                int oo = gid + (p >> 1) * 8;
                float v = acc[nj][p];
                __half h = __float2half_rn(v);
                smh[tH + dd * 24 + oo] = h;
                smh[tL + dd * 24 + oo] = __float2half_rn(v - __half2float(h));
            }
        }
        __syncthreads();

        // ---- energy: E += qT * kT^T  (B frags hoisted out of im loop) ----
        u32 kh[3][2], kl[3][2];
        {
            u32 r4[4];
            u32 beP = (8u * (3 * nwq + pl) + prow) * 24 + pcol8;
            ldsm_x4(r4, sb + 2u * (E_KTH + beP));
            kh[0][0] = r4[0]; kh[0][1] = r4[1]; kh[1][0] = r4[2]; kh[1][1] = r4[3];
            ldsm_x4(r4, sb + 2u * (E_KTL + beP));
            kl[0][0] = r4[0]; kl[0][1] = r4[1]; kl[1][0] = r4[2]; kl[1][1] = r4[3];
            u32 be2 = (8u * (3 * nwq + 2) + brow) * 24 + bcol8;
            ldsm_x2(kh[2], sb + 2u * (E_KTH + be2));
            ldsm_x2(kl[2], sb + 2u * (E_KTL + be2));
        }
        #pragma unroll
        for (int im = 0; im < 3; im++) {
            u32 ah[4], al[4];
            u32 ae = (16 * (3 * mw + im) + arow) * 24 + acol8;
            ldsm_x4(ah, sb + 2u * (E_QTH + ae));
            ldsm_x4(al, sb + 2u * (E_QTL + ae));
            #pragma unroll
            for (int in = 0; in < 3; in++) {
                mma_hf(E[im][in], ah, kh[in]);
                mma_hf(E[im][in], ah, kl[in]);
                mma_hf(E[im][in], al, kh[in]);
            }
        }
        // next X-store touches only XH/XL (disjoint from qT/kT); the sync after
        // it orders energy reads against the next projection's qT/kT writes.
    }

    float* dst = g_partial + ((size_t)(b * NBLK1 + g)) * Dn * Dn;
    #pragma unroll
    for (int im = 0; im < 3; im++)
        #pragma unroll
        for (int in = 0; in < 3; in++) {
            int r = 16 * (3 * mw + im) + gid;
            int c = 8 * (3 * nwq + in) + 2 * tig;
            *reinterpret_cast<float2*>(&dst[(size_t)r * Dn + c]) =
                make_float2(E[im][in][0], E[im][in][1]);
            *reinterpret_cast<float2*>(&dst[(size_t)(r + 8) * Dn + c]) =
                make_float2(E[im][in][2], E[im][in][3]);
        }
}

// ============================================================================
// Kernel 2: reduce partials, softmax over e, fold gamma. Stores [b][d][e].
// ============================================================================
__global__ void k_softmax(const float* __restrict__ gamma) {
    const int b = blockIdx.y, d = blockIdx.x;
    const int e = threadIdx.x;
    float v = 0.f;
    for (int g = 0; g < NBLK1; g++)
        v += g_partial[(((size_t)b * NBLK1 + g) * Dn + d) * Dn + e];
    __shared__ float sv[Dn];
    __shared__ float red;
    sv[e] = v;
    __syncthreads();
    if (e == 0) { float m = sv[0]; for (int i = 1; i < Dn; i++) m = fmaxf(m, sv[i]); red = m; }
    __syncthreads();
    float pe = expf(v - red);
    sv[e] = pe;
    __syncthreads();
    if (e == 0) { float s = 0.f; for (int i = 0; i < Dn; i++) s += sv[i]; red = s; }
    __syncthreads();
    g_attn[((size_t)b * Dn + d) * Dn + e] = gamma[0] * pe / red;
}

// ============================================================================
// Kernel 3: fused V projection + attention apply + residual, split-bf16 MMA.
// x4-paired B ldmatrix in both GEMMs, register-prefetch of next X column,
// 64-bit staging stores.
// ============================================================================
#define S_WVH 0
#define S_WVL 4608
#define S_XH  9216
#define S_XL  15872
#define S_VH  22528
#define S_VL  29184
#define S_AH  35840
#define S_AL  45824
#define S_TOT 55808

__global__ void __launch_bounds__(256, 2) k_out(
    const float* __restrict__ x, const float* __restrict__ Wv,
    const float* __restrict__ bv, float* __restrict__ out)
{
    extern __shared__ __align__(16) u32 smw[];
    __nv_bfloat16* smb = reinterpret_cast<__nv_bfloat16*>(smw);
    u64* smq = reinterpret_cast<u64*>(smw);
    const u32 sb = (u32)__cvta_generic_to_shared(smw);

    const int b = blockIdx.y, g = blockIdx.x, t = threadIdx.x;
    const int w = t >> 5, l = t & 31;

    for (int i = t; i < Cn * Cn; i += 256) {
        int c = i >> 6, cc = i & 63;
        float v = Wv[i];
        __nv_bfloat16 h = __float2bfloat16(v);
        smb[S_WVH + c * 72 + cc] = h;
        smb[S_WVL + c * 72 + cc] = __float2bfloat16(v - __bfloat162float(h));
    }
    const float* Ab = g_attn + (size_t)b * Dn * Dn;
    for (int i = t; i < Dn * Dn; i += 256) {
        int d = i / 96, e = i % 96;
        float v = Ab[i];
        __nv_bfloat16 h = __float2bfloat16(v);
        smb[S_AH + d * 104 + e] = h;
        smb[S_AL + d * 104 + e] = __float2bfloat16(v - __bfloat162float(h));
    }

    const int mi = w & 3, nj0 = (w >> 2) * 6;
    const int gid = l >> 2, tig = l & 3;
    const float bv0 = bv[16 * mi + gid], bv1 = bv[16 * mi + gid + 8];

    const int arow  = (l & 7) + (l & 8);
    const int acol8 = ((l >> 4) & 1) * 8;
    const int eWa = (16 * mi + arow) * 72 + acol8;
    const int eVa = (16 * mi + arow) * 104 + acol8;
    const int xrow = (l & 15);
    const int pl   = (l >> 4) & 1;
    const int prow = (l & 7);
    const int pcol8 = ((l >> 3) & 1) * 8;

    const int cp = t >> 2;
    const int d0 = (t & 3) * 24;

    const float* xb = x   + (size_t)b * Cn * HWn * Dn;
    float*       ob = out + (size_t)b * Cn * HWn * Dn;

    // prefetch X column 0
    float4 xf[6];
    {
        const float4* src = reinterpret_cast<const float4*>(
            xb + ((size_t)cp * HWn + (size_t)g * HWPC) * Dn + d0);
        #pragma unroll
        for (int j = 0; j < 6; j++) xf[j] = src[j];
    }

    __syncthreads();

    for (int it = 0; it < HWPC; ++it) {
        const int hw = g * HWPC + it;

        // ---- stage X from prefetched regs, 64-bit stores ----
        #pragma unroll
        for (int j = 0; j < 6; j++) {
            float4 f = xf[j];
            int e0 = cp * 104 + d0 + 4 * j;
            u32 h0 = packbf2(f.x, f.y), h1 = packbf2(f.z, f.w);
            u32 l0 = packbf2(f.x - bflo(h0), f.y - bfhi(h0));
            u32 l1 = packbf2(f.z - bflo(h1), f.w - bfhi(h1));
            smq[(S_XH + e0) >> 2] = mk64(h0, h1);
            smq[(S_XL + e0) >> 2] = mk64(l0, l1);
        }
        __syncthreads();

        if (it + 1 < HWPC) {
            const float4* src = reinterpret_cast<const float4*>(
                xb + ((size_t)cp * HWn + (size_t)(hw + 1)) * Dn + d0);
            #pragma unroll
            for (int j = 0; j < 6; j++) xf[j] = src[j];
        }

        // ---- GEMM-A: acc = Wv * X + bv (B x4.trans-paired) ----
        float acc[6][4];
        #pragma unroll
        for (int nj = 0; nj < 6; nj++) {
            acc[nj][0] = bv0; acc[nj][1] = bv0; acc[nj][2] = bv1; acc[nj][3] = bv1;
        }
        #pragma unroll
        for (int ks = 0; ks < 4; ks++) {
            u32 ah[4], al[4];
            ldsm_x4(ah, sb + 2u * (S_WVH + eWa + 16 * ks));
            ldsm_x4(al, sb + 2u * (S_WVL + eWa + 16 * ks));
            #pragma unroll
            for (int njp = 0; njp < 6; njp += 2) {
                u32 rh[4], rl[4];
                u32 beP = (16 * ks + xrow) * 104 + 8 * (nj0 + njp + pl);
                ldsm_x4t(rh, sb + 2u * (S_XH + beP));
                ldsm_x4t(rl, sb + 2u * (S_XL + beP));
                mma_bf(acc[njp],     ah, rh);     mma_bf(acc[njp],     ah, rl);     mma_bf(acc[njp],     al, rh);
                mma_bf(acc[njp + 1], ah, rh + 2); mma_bf(acc[njp + 1], ah, rl + 2); mma_bf(acc[njp + 1], al, rh + 2);
            }
        }

        // ---- split V to SMEM ----
        #pragma unroll
        for (int nj = 0; nj < 6; nj++) {
            int e  = 8 * (nj0 + nj) + 2 * tig;
            int r0 = 16 * mi + gid, r1 = r0 + 8;
            u32 h0 = packbf2(acc[nj][0], acc[nj][1]);
            u32 p0 = packbf2(acc[nj][0] - bflo(h0), acc[nj][1] - bfhi(h0));
            u32 h1 = packbf2(acc[nj][2], acc[nj][3]);
            u32 p1 = packbf2(acc[nj][2] - bflo(h1), acc[nj][3] - bfhi(h1));
            smw[(S_VH + r0 * 104 + e) >> 1] = h0;
            smw[(S_VL + r0 * 104 + e) >> 1] = p0;
            smw[(S_VH + r1 * 104 + e) >> 1] = h1;
            smw[(S_VL + r1 * 104 + e) >> 1] = p1;
        }
        __syncthreads();

        // ---- GEMM-B: acc = V * A'^T (B x4-paired) ----
        #pragma unroll
        for (int nj = 0; nj < 6; nj++) {
            acc[nj][0] = 0.f; acc[nj][1] = 0.f; acc[nj][2] = 0.f; acc[nj][3] = 0.f;
        }
        #pragma unroll
        for (int ks = 0; ks < 6; ks++) {
            u32 ah[4], al[4];
            ldsm_x4(ah, sb + 2u * (S_VH + eVa + 16 * ks));
            ldsm_x4(al, sb + 2u * (S_VL + eVa + 16 * ks));
            #pragma unroll
            for (int njp = 0; njp < 6; njp += 2) {
                u32 rh[4], rl[4];
                u32 beP = (8 * (nj0 + njp + pl) + prow) * 104 + 16 * ks + pcol8;
                ldsm_x4(rh, sb + 2u * (S_AH + beP));
                ldsm_x4(rl, sb + 2u * (S_AL + beP));
                mma_bf(acc[njp],     ah, rh);     mma_bf(acc[njp],     ah, rl);     mma_bf(acc[njp],     al, rh);
                mma_bf(acc[njp + 1], ah, rh + 2); mma_bf(acc[njp + 1], ah, rl + 2); mma_bf(acc[njp + 1], al, rh + 2);
            }
        }

        // ---- residual (X = hi + lo) + store ----
        #pragma unroll
        for (int nj = 0; nj < 6; nj++) {
            int d  = 8 * (nj0 + nj) + 2 * tig;
            int r0 = 16 * mi + gid, r1 = r0 + 8;
            u32 xh0 = smw[(S_XH + r0 * 104 + d) >> 1], xl0 = smw[(S_XL + r0 * 104 + d) >> 1];
            u32 xh1 = smw[(S_XH + r1 * 104 + d) >> 1], xl1 = smw[(S_XL + r1 * 104 + d) >> 1];
            float2 o0, o1;
            o0.x = acc[nj][0] + bflo(xh0) + bflo(xl0);
            o0.y = acc[nj][1] + bfhi(xh0) + bfhi(xl0);
            o1.x = acc[nj][2] + bflo(xh1) + bflo(xl1);
            o1.y = acc[nj][3] + bfhi(xh1) + bfhi(xl1);
            *reinterpret_cast<float2*>(ob + ((size_t)r0 * HWn + hw) * Dn + d) = o0;
            *reinterpret_cast<float2*>(ob + ((size_t)r1 * HWn + hw) * Dn + d) = o1;
        }
        __syncthreads();
    }
}

extern "C" void kernel_launch(void* const* d_in, const int* in_sizes, int n_in,
                              void* d_out, int out_size) {
    (void)in_sizes; (void)n_in; (void)out_size;
    const float* x     = (const float*)d_in[0];
    const float* Wq    = (const float*)d_in[1];
    const float* bq    = (const float*)d_in[2];
    const float* Wk    = (const float*)d_in[3];
    const float* bk    = (const float*)d_in[4];
    const float* Wv    = (const float*)d_in[5];
    const float* bv    = (const float*)d_in[6];
    const float* gamma = (const float*)d_in[7];
    float* out = (float*)d_out;

    cudaFuncSetAttribute(k_energy, cudaFuncAttributeMaxDynamicSharedMemorySize, E_TOT * 2);
    cudaFuncSetAttribute(k_out,    cudaFuncAttributeMaxDynamicSharedMemorySize, S_TOT * 2);

    k_energy<<<dim3(NBLK1, Bn), 256, E_TOT * 2>>>(x, Wq, bq, Wk, bk);
    k_softmax<<<dim3(Dn, Bn), Dn>>>(gamma);
    k_out<<<dim3(NBLK3, Bn), 256, S_TOT * 2>>>(x, Wv, bv, out);
}

// round 14
// speedup vs baseline: 2.0713x; 1.0687x over previous
#include <cuda_runtime.h>
#include <cuda_bf16.h>
#include <cuda_fp16.h>

#define Bn 2
#define Cn 64
#define CQn 16
#define HWn 9216
#define Dn 96
#define NBLK1 128
#define HWPB1 72      // HWn / NBLK1
#define HWPC 16       // hw columns per CTA in k_out
#define NBLK3 (HWn / HWPC)   // 576

typedef unsigned long long u64;
typedef unsigned int u32;

// Scratch (no runtime allocation allowed)
__device__ float g_partial[Bn * NBLK1 * Dn * Dn];  // per-block energy partials
__device__ float g_attn[Bn * Dn * Dn];             // gamma * softmax(energy), [b][d][e]

// ---- bf16 split helpers (k_out) ----
__device__ __forceinline__ u32 packbf2(float f0, float f1) {
    u32 r; asm("cvt.rn.bf16x2.f32 %0, %1, %2;" : "=r"(r) : "f"(f1), "f"(f0)); return r;
}
__device__ __forceinline__ float bflo(u32 p) { return __uint_as_float(p << 16); }
__device__ __forceinline__ float bfhi(u32 p) { return __uint_as_float(p & 0xffff0000u); }

// ---- fp16 split helpers (k_energy) ----
__device__ __forceinline__ u32 packhf2(float f0, float f1) {
    u32 r; asm("cvt.rn.f16x2.f32 %0, %1, %2;" : "=r"(r) : "f"(f1), "f"(f0)); return r;
}
__device__ __forceinline__ float hflo(u32 p) {
    return __half2float(__ushort_as_half((unsigned short)(p & 0xffffu)));
}
__device__ __forceinline__ float hfhi(u32 p) {
    return __half2float(__ushort_as_half((unsigned short)(p >> 16)));
}

// ---- ldmatrix / mma wrappers ----
__device__ __forceinline__ void ldsm_x4(u32* r, u32 addr) {
    asm volatile("ldmatrix.sync.aligned.m8n8.x4.shared.b16 {%0,%1,%2,%3}, [%4];"
        : "=r"(r[0]), "=r"(r[1]), "=r"(r[2]), "=r"(r[3]) : "r"(addr));
}
__device__ __forceinline__ void ldsm_x4t(u32* r, u32 addr) {
    asm volatile("ldmatrix.sync.aligned.m8n8.x4.trans.shared.b16 {%0,%1,%2,%3}, [%4];"
        : "=r"(r[0]), "=r"(r[1]), "=r"(r[2]), "=r"(r[3]) : "r"(addr));
}
__device__ __forceinline__ void ldsm_x2(u32* r, u32 addr) {
    asm volatile("ldmatrix.sync.aligned.m8n8.x2.shared.b16 {%0,%1}, [%2];"
        : "=r"(r[0]), "=r"(r[1]) : "r"(addr));
}
__device__ __forceinline__ void ldsm_x2t(u32* r, u32 addr) {
    asm volatile("ldmatrix.sync.aligned.m8n8.x2.trans.shared.b16 {%0,%1}, [%2];"
        : "=r"(r[0]), "=r"(r[1]) : "r"(addr));
}
__device__ __forceinline__ void mma_bf(float* d, const u32* a, const u32* b) {
    asm volatile("mma.sync.aligned.m16n8k16.row.col.f32.bf16.bf16.f32 "
        "{%0,%1,%2,%3}, {%4,%5,%6,%7}, {%8,%9}, {%0,%1,%2,%3};"
        : "+f"(d[0]), "+f"(d[1]), "+f"(d[2]), "+f"(d[3])
        : "r"(a[0]), "r"(a[1]), "r"(a[2]), "r"(a[3]), "r"(b[0]), "r"(b[1]));
}
__device__ __forceinline__ void mma_hf(float* d, const u32* a, const u32* b) {
    asm volatile("mma.sync.aligned.m16n8k16.row.col.f32.f16.f16.f32 "
        "{%0,%1,%2,%3}, {%4,%5,%6,%7}, {%8,%9}, {%0,%1,%2,%3};"
        : "+f"(d[0]), "+f"(d[1]), "+f"(d[2]), "+f"(d[3])
        : "r"(a[0]), "r"(a[1]), "r"(a[2]), "r"(a[3]), "r"(b[0]), "r"(b[1]));
}

// ============================================================================
// Kernel 1: fused q/k projection + energy, split-fp16 MMA.
// q/k stored NON-transposed [o][d] with packed STS.32 (was 24 scalar STS.16
// per thread); energy phase reads via ldmatrix.trans. X staging merged to
// STS.128.
// ============================================================================

#define E_WQH 0                       // Wq hi [16][72]
#define E_WQL 1152
#define E_WKH 2304
#define E_WKL 3456
#define E_XH  4608                    // X  hi [64 c][104 d]
#define E_XL  11264
#define E_QH  17920                   // q hi [16 o][104 d]
#define E_QL  19584
#define E_KH  21248                   // k hi [16 o][104 e]
#define E_KL  22912
#define E_TOT 24576                   // *2 = 49152 bytes

__global__ void __launch_bounds__(256, 2) k_energy(
    const float* __restrict__ x, const float* __restrict__ Wq,
    const float* __restrict__ bq, const float* __restrict__ Wk,
    const float* __restrict__ bk)
{
    extern __shared__ __align__(16) u32 smw[];
    __half* smh = reinterpret_cast<__half*>(smw);
    const u32 sb = (u32)__cvta_generic_to_shared(smw);

    const int b = blockIdx.y, g = blockIdx.x, t = threadIdx.x;
    const int w = t >> 5, l = t & 31;

    // one-time: split Wq, Wk into hi/lo fp16
    for (int i = t; i < CQn * Cn; i += 256) {
        int o = i >> 6, c = i & 63;
        float vq = Wq[i], vk = Wk[i];
        __half hq = __float2half_rn(vq), hk = __float2half_rn(vk);
        smh[E_WQH + o * 72 + c] = hq;
        smh[E_WQL + o * 72 + c] = __float2half_rn(vq - __half2float(hq));
        smh[E_WKH + o * 72 + c] = hk;
        smh[E_WKL + o * 72 + c] = __float2half_rn(vk - __half2float(hk));
    }

    const int qk  = w >> 2;
    const int nb  = (w & 3) * 3;
    const int gid = l >> 2, tig = l & 3;
    const int waH = qk ? E_WKH : E_WQH;
    const int waL = qk ? E_WKL : E_WQL;
    const int tH  = qk ? E_KH : E_QH;
    const int tL  = qk ? E_KL : E_QL;
    const float* bias = qk ? bk : bq;
    const float bs0 = bias[gid], bs1 = bias[gid + 8];

    // lane-constant ldmatrix address parts
    const int arow  = (l & 7) + (l & 8);          // A non-trans: m-row 0..15
    const int acol8 = ((l >> 4) & 1) * 8;         // A non-trans: k-half
    const int xrow  = (l & 15);                   // B trans: k-row 0..15
    const int pl    = (l >> 4) & 1;               // pair-tile select (x4)
    // A trans (energy): k-row and m-col halves
    const int atrow = (l & 7) + ((l >> 4) & 1) * 8;
    const int amcol = ((l >> 3) & 1) * 8;

    const int mw = w >> 2, nwq = w & 3;

    float E[3][3][4];
    #pragma unroll
    for (int im = 0; im < 3; im++)
        #pragma unroll
        for (int in = 0; in < 3; in++)
            #pragma unroll
            for (int p = 0; p < 4; p++) E[im][in][p] = 0.f;

    const int cp = t >> 2;
    const int d0 = (t & 3) * 24;
    const float* xb = x + (size_t)b * Cn * HWn * Dn;

    // prefetch X column 0
    float4 xf[6];
    {
        const float4* src = reinterpret_cast<const float4*>(
            xb + ((size_t)cp * HWn + (size_t)g * HWPB1) * Dn + d0);
        #pragma unroll
        for (int j = 0; j < 6; j++) xf[j] = src[j];
    }

    __syncthreads();

    for (int it = 0; it < HWPB1; ++it) {
        // ---- stage X: split hi/lo fp16, merged 128-bit stores ----
        #pragma unroll
        for (int jp = 0; jp < 3; jp++) {
            float4 fa = xf[2 * jp], fb = xf[2 * jp + 1];
            int e0 = cp * 104 + d0 + 8 * jp;
            u32 h0 = packhf2(fa.x, fa.y), h1 = packhf2(fa.z, fa.w);
            u32 h2 = packhf2(fb.x, fb.y), h3 = packhf2(fb.z, fb.w);
            u32 l0 = packhf2(fa.x - hflo(h0), fa.y - hfhi(h0));
            u32 l1 = packhf2(fa.z - hflo(h1), fa.w - hfhi(h1));
            u32 l2 = packhf2(fb.x - hflo(h2), fb.y - hfhi(h2));
            u32 l3 = packhf2(fb.z - hflo(h3), fb.w - hfhi(h3));
            *reinterpret_cast<uint4*>(&smh[E_XH + e0]) = make_uint4(h0, h1, h2, h3);
            *reinterpret_cast<uint4*>(&smh[E_XL + e0]) = make_uint4(l0, l1, l2, l3);
        }
        __syncthreads();

        // issue next column's LDGs; consumed next iteration (hides DRAM lat)
        if (it + 1 < HWPB1) {
            const float4* src = reinterpret_cast<const float4*>(
                xb + ((size_t)cp * HWn + (size_t)(g * HWPB1 + it + 1)) * Dn + d0);
            #pragma unroll
            for (int j = 0; j < 6; j++) xf[j] = src[j];
        }

        // ---- projection: acc = W * X + bias (3 n-tiles; B x4-paired) ----
        float acc[3][4];
        #pragma unroll
        for (int nj = 0; nj < 3; nj++) {
            acc[nj][0] = bs0; acc[nj][1] = bs0; acc[nj][2] = bs1; acc[nj][3] = bs1;
        }
        #pragma unroll
        for (int ks = 0; ks < 4; ks++) {
            u32 ah[4], al[4];
            ldsm_x4(ah, sb + 2u * (waH + arow * 72 + acol8 + 16 * ks));
            ldsm_x4(al, sb + 2u * (waL + arow * 72 + acol8 + 16 * ks));
            u32 rh[4], rl[4];
            u32 beP = (16 * ks + xrow) * 104 + 8 * (nb + pl);
            ldsm_x4t(rh, sb + 2u * (E_XH + beP));
            ldsm_x4t(rl, sb + 2u * (E_XL + beP));
            mma_hf(acc[0], ah, rh);     mma_hf(acc[0], ah, rl);     mma_hf(acc[0], al, rh);
            mma_hf(acc[1], ah, rh + 2); mma_hf(acc[1], ah, rl + 2); mma_hf(acc[1], al, rh + 2);
            u32 bh2[2], bl2[2];
            u32 be2 = (16 * ks + xrow) * 104 + 8 * (nb + 2);
            ldsm_x2t(bh2, sb + 2u * (E_XH + be2));
            ldsm_x2t(bl2, sb + 2u * (E_XL + be2));
            mma_hf(acc[2], ah, bh2); mma_hf(acc[2], ah, bl2); mma_hf(acc[2], al, bh2);
        }

        // ---- write q/k NON-transposed [o][104 d], packed 32-bit stores ----
        #pragma unroll
        for (int nj = 0; nj < 3; nj++) {
            int dc = 8 * (nb + nj) + 2 * tig;
            u32 h01 = packhf2(acc[nj][0], acc[nj][1]);
            u32 l01 = packhf2(acc[nj][0] - hflo(h01), acc[nj][1] - hfhi(h01));
            u32 h23 = packhf2(acc[nj][2], acc[nj][3]);
            u32 l23 = packhf2(acc[nj][2] - hflo(h23), acc[nj][3] - hfhi(h23));
            int b0 = gid * 104 + dc;
            int b1 = (gid + 8) * 104 + dc;
            smw[(tH + b0) >> 1] = h01;
            smw[(tL + b0) >> 1] = l01;
            smw[(tH + b1) >> 1] = h23;
            smw[(tL + b1) >> 1] = l23;
        }
        __syncthreads();

        // ---- energy: E += q^T k  (A/B via ldmatrix.trans from [o][*]) ----
        u32 kh[3][2], kl[3][2];
        {
            u32 r4[4];
            u32 beP = xrow * 104 + 8 * (3 * nwq + pl);
            ldsm_x4t(r4, sb + 2u * (E_KH + beP));
            kh[0][0] = r4[0]; kh[0][1] = r4[1]; kh[1][0] = r4[2]; kh[1][1] = r4[3];
            ldsm_x4t(r4, sb + 2u * (E_KL + beP));
            kl[0][0] = r4[0]; kl[0][1] = r4[1]; kl[1][0] = r4[2]; kl[1][1] = r4[3];
            u32 be2 = xrow * 104 + 8 * (3 * nwq + 2);
            ldsm_x2t(kh[2], sb + 2u * (E_KH + be2));
            ldsm_x2t(kl[2], sb + 2u * (E_KL + be2));
        }
        #pragma unroll
        for (int im = 0; im < 3; im++) {
            u32 ah[4], al[4];
            u32 ae = atrow * 104 + 16 * (3 * mw + im) + amcol;
            ldsm_x4t(ah, sb + 2u * (E_QH + ae));
            ldsm_x4t(al, sb + 2u * (E_QL + ae));
            #pragma unroll
            for (int in = 0; in < 3; in++) {
                mma_hf(E[im][in], ah, kh[in]);
                mma_hf(E[im][in], ah, kl[in]);
                mma_hf(E[im][in], al, kh[in]);
            }
        }
        // next X-store touches only XH/XL (disjoint from q/k); the sync after
        // it orders energy reads against the next projection's q/k writes.
    }

    float* dst = g_partial + ((size_t)(b * NBLK1 + g)) * Dn * Dn;
    #pragma unroll
    for (int im = 0; im < 3; im++)
        #pragma unroll
        for (int in = 0; in < 3; in++) {
            int r = 16 * (3 * mw + im) + gid;
            int c = 8 * (3 * nwq + in) + 2 * tig;
            *reinterpret_cast<float2*>(&dst[(size_t)r * Dn + c]) =
                make_float2(E[im][in][0], E[im][in][1]);
            *reinterpret_cast<float2*>(&dst[(size_t)(r + 8) * Dn + c]) =
                make_float2(E[im][in][2], E[im][in][3]);
        }
}

// ============================================================================
// Kernel 2: reduce partials, softmax over e, fold gamma. Stores [b][d][e].
// ============================================================================
__global__ void k_softmax(const float* __restrict__ gamma) {
    const int b = blockIdx.y, d = blockIdx.x;
    const int e = threadIdx.x;
    float v = 0.f;
    for (int g = 0; g < NBLK1; g++)
        v += g_partial[(((size_t)b * NBLK1 + g) * Dn + d) * Dn + e];
    __shared__ float sv[Dn];
    __shared__ float red;
    sv[e] = v;
    __syncthreads();
    if (e == 0) { float m = sv[0]; for (int i = 1; i < Dn; i++) m = fmaxf(m, sv[i]); red = m; }
    __syncthreads();
    float pe = expf(v - red);
    sv[e] = pe;
    __syncthreads();
    if (e == 0) { float s = 0.f; for (int i = 0; i < Dn; i++) s += sv[i]; red = s; }
    __syncthreads();
    g_attn[((size_t)b * Dn + d) * Dn + e] = gamma[0] * pe / red;
}

// ============================================================================
// Kernel 3: fused V projection + attention apply + residual, split-bf16 MMA.
// X staging merged to 128-bit stores.
// ============================================================================
#define S_WVH 0
#define S_WVL 4608
#define S_XH  9216
#define S_XL  15872
#define S_VH  22528
#define S_VL  29184
#define S_AH  35840
#define S_AL  45824
#define S_TOT 55808

__global__ void __launch_bounds__(256, 2) k_out(
    const float* __restrict__ x, const float* __restrict__ Wv,
    const float* __restrict__ bv, float* __restrict__ out)
{
    extern __shared__ __align__(16) u32 smw[];
    __nv_bfloat16* smb = reinterpret_cast<__nv_bfloat16*>(smw);
    const u32 sb = (u32)__cvta_generic_to_shared(smw);

    const int b = blockIdx.y, g = blockIdx.x, t = threadIdx.x;
    const int w = t >> 5, l = t & 31;

    for (int i = t; i < Cn * Cn; i += 256) {
        int c = i >> 6, cc = i & 63;
        float v = Wv[i];
        __nv_bfloat16 h = __float2bfloat16(v);
        smb[S_WVH + c * 72 + cc] = h;
        smb[S_WVL + c * 72 + cc] = __float2bfloat16(v - __bfloat162float(h));
    }
    const float* Ab = g_attn + (size_t)b * Dn * Dn;
    for (int i = t; i < Dn * Dn; i += 256) {
        int d = i / 96, e = i % 96;
        float v = Ab[i];
        __nv_bfloat16 h = __float2bfloat16(v);
        smb[S_AH + d * 104 + e] = h;
        smb[S_AL + d * 104 + e] = __float2bfloat16(v - __bfloat162float(h));
    }

    const int mi = w & 3, nj0 = (w >> 2) * 6;
    const int gid = l >> 2, tig = l & 3;
    const float bv0 = bv[16 * mi + gid], bv1 = bv[16 * mi + gid + 8];

    const int arow  = (l & 7) + (l & 8);
    const int acol8 = ((l >> 4) & 1) * 8;
    const int eWa = (16 * mi + arow) * 72 + acol8;
    const int eVa = (16 * mi + arow) * 104 + acol8;
    const int xrow = (l & 15);
    const int pl   = (l >> 4) & 1;
    const int prow = (l & 7);
    const int pcol8 = ((l >> 3) & 1) * 8;

    const int cp = t >> 2;
    const int d0 = (t & 3) * 24;

    const float* xb = x   + (size_t)b * Cn * HWn * Dn;
    float*       ob = out + (size_t)b * Cn * HWn * Dn;

    // prefetch X column 0
    float4 xf[6];
    {
        const float4* src = reinterpret_cast<const float4*>(
            xb + ((size_t)cp * HWn + (size_t)g * HWPC) * Dn + d0);
        #pragma unroll
        for (int j = 0; j < 6; j++) xf[j] = src[j];
    }

    __syncthreads();

    for (int it = 0; it < HWPC; ++it) {
        const int hw = g * HWPC + it;

        // ---- stage X: split hi/lo bf16, merged 128-bit stores ----
        #pragma unroll
        for (int jp = 0; jp < 3; jp++) {
            float4 fa = xf[2 * jp], fb = xf[2 * jp + 1];
            int e0 = cp * 104 + d0 + 8 * jp;
            u32 h0 = packbf2(fa.x, fa.y), h1 = packbf2(fa.z, fa.w);
            u32 h2 = packbf2(fb.x, fb.y), h3 = packbf2(fb.z, fb.w);
            u32 l0 = packbf2(fa.x - bflo(h0), fa.y - bfhi(h0));
            u32 l1 = packbf2(fa.z - bflo(h1), fa.w - bfhi(h1));
            u32 l2 = packbf2(fb.x - bflo(h2), fb.y - bfhi(h2));
            u32 l3 = packbf2(fb.z - bflo(h3), fb.w - bfhi(h3));
            *reinterpret_cast<uint4*>(&smb[S_XH + e0]) = make_uint4(h0, h1, h2, h3);
            *reinterpret_cast<uint4*>(&smb[S_XL + e0]) = make_uint4(l0, l1, l2, l3);
        }
        __syncthreads();

        if (it + 1 < HWPC) {
            const float4* src = reinterpret_cast<const float4*>(
                xb + ((size_t)cp * HWn + (size_t)(hw + 1)) * Dn + d0);
            #pragma unroll
            for (int j = 0; j < 6; j++) xf[j] = src[j];
        }

        // ---- GEMM-A: acc = Wv * X + bv (B x4.trans-paired) ----
        float acc[6][4];
        #pragma unroll
        for (int nj = 0; nj < 6; nj++) {
            acc[nj][0] = bv0; acc[nj][1] = bv0; acc[nj][2] = bv1; acc[nj][3] = bv1;
        }
        #pragma unroll
        for (int ks = 0; ks < 4; ks++) {
            u32 ah[4], al[4];
            ldsm_x4(ah, sb + 2u * (S_WVH + eWa + 16 * ks));
            ldsm_x4(al, sb + 2u * (S_WVL + eWa + 16 * ks));
            #pragma unroll
            for (int njp = 0; njp < 6; njp += 2) {
                u32 rh[4], rl[4];
                u32 beP = (16 * ks + xrow) * 104 + 8 * (nj0 + njp + pl);
                ldsm_x4t(rh, sb + 2u * (S_XH + beP));
                ldsm_x4t(rl, sb + 2u * (S_XL + beP));
                mma_bf(acc[njp],     ah, rh);     mma_bf(acc[njp],     ah, rl);     mma_bf(acc[njp],     al, rh);
                mma_bf(acc[njp + 1], ah, rh + 2); mma_bf(acc[njp + 1], ah, rl + 2); mma_bf(acc[njp + 1], al, rh + 2);
            }
        }

        // ---- split V to SMEM ----
        #pragma unroll
        for (int nj = 0; nj < 6; nj++) {
            int e  = 8 * (nj0 + nj) + 2 * tig;
            int r0 = 16 * mi + gid, r1 = r0 + 8;
            u32 h0 = packbf2(acc[nj][0], acc[nj][1]);
            u32 p0 = packbf2(acc[nj][0] - bflo(h0), acc[nj][1] - bfhi(h0));
            u32 h1 = packbf2(acc[nj][2], acc[nj][3]);
            u32 p1 = packbf2(acc[nj][2] - bflo(h1), acc[nj][3] - bfhi(h1));
            smw[(S_VH + r0 * 104 + e) >> 1] = h0;
            smw[(S_VL + r0 * 104 + e) >> 1] = p0;
            smw[(S_VH + r1 * 104 + e) >> 1] = h1;
            smw[(S_VL + r1 * 104 + e) >> 1] = p1;
        }
        __syncthreads();

        // ---- GEMM-B: acc = V * A'^T (B x4-paired) ----
        #pragma unroll
        for (int nj = 0; nj < 6; nj++) {
            acc[nj][0] = 0.f; acc[nj][1] = 0.f; acc[nj][2] = 0.f; acc[nj][3] = 0.f;
        }
        #pragma unroll
        for (int ks = 0; ks < 6; ks++) {
            u32 ah[4], al[4];
            ldsm_x4(ah, sb + 2u * (S_VH + eVa + 16 * ks));
            ldsm_x4(al, sb + 2u * (S_VL + eVa + 16 * ks));
            #pragma unroll
            for (int njp = 0; njp < 6; njp += 2) {
                u32 rh[4], rl[4];
                u32 beP = (8 * (nj0 + njp + pl) + prow) * 104 + 16 * ks + pcol8;
                ldsm_x4(rh, sb + 2u * (S_AH + beP));
                ldsm_x4(rl, sb + 2u * (S_AL + beP));
                mma_bf(acc[njp],     ah, rh);     mma_bf(acc[njp],     ah, rl);     mma_bf(acc[njp],     al, rh);
                mma_bf(acc[njp + 1], ah, rh + 2); mma_bf(acc[njp + 1], ah, rl + 2); mma_bf(acc[njp + 1], al, rh + 2);
            }
        }

        // ---- residual (X = hi + lo) + store ----
        #pragma unroll
        for (int nj = 0; nj < 6; nj++) {
            int d  = 8 * (nj0 + nj) + 2 * tig;
            int r0 = 16 * mi + gid, r1 = r0 + 8;
            u32 xh0 = smw[(S_XH + r0 * 104 + d) >> 1], xl0 = smw[(S_XL + r0 * 104 + d) >> 1];
            u32 xh1 = smw[(S_XH + r1 * 104 + d) >> 1], xl1 = smw[(S_XL + r1 * 104 + d) >> 1];
            float2 o0, o1;
            o0.x = acc[nj][0] + bflo(xh0) + bflo(xl0);
            o0.y = acc[nj][1] + bfhi(xh0) + bfhi(xl0);
            o1.x = acc[nj][2] + bflo(xh1) + bflo(xl1);
            o1.y = acc[nj][3] + bfhi(xh1) + bfhi(xl1);
            *reinterpret_cast<float2*>(ob + ((size_t)r0 * HWn + hw) * Dn + d) = o0;
            *reinterpret_cast<float2*>(ob + ((size_t)r1 * HWn + hw) * Dn + d) = o1;
        }
        __syncthreads();
    }
}

extern "C" void kernel_launch(void* const* d_in, const int* in_sizes, int n_in,
                              void* d_out, int out_size) {
    (void)in_sizes; (void)n_in; (void)out_size;
    const float* x     = (const float*)d_in[0];
    const float* Wq    = (const float*)d_in[1];
    const float* bq    = (const float*)d_in[2];
    const float* Wk    = (const float*)d_in[3];
    const float* bk    = (const float*)d_in[4];
    const float* Wv    = (const float*)d_in[5];
    const float* bv    = (const float*)d_in[6];
    const float* gamma = (const float*)d_in[7];
    float* out = (float*)d_out;

    cudaFuncSetAttribute(k_energy, cudaFuncAttributeMaxDynamicSharedMemorySize, E_TOT * 2);
    cudaFuncSetAttribute(k_out,    cudaFuncAttributeMaxDynamicSharedMemorySize, S_TOT * 2);

    k_energy<<<dim3(NBLK1, Bn), 256, E_TOT * 2>>>(x, Wq, bq, Wk, bk);
    k_softmax<<<dim3(Dn, Bn), Dn>>>(gamma);
    k_out<<<dim3(NBLK3, Bn), 256, S_TOT * 2>>>(x, Wv, bv, out);
}

// round 15
// speedup vs baseline: 2.4141x; 1.1655x over previous
#include <cuda_runtime.h>
#include <cuda_bf16.h>
#include <cuda_fp16.h>

#define Bn 2
#define Cn 64
#define CQn 16
#define HWn 9216
#define Dn 96
#define NBLK1 128
#define HWPB1 72      // HWn / NBLK1
#define HWPC 16       // hw columns per CTA in k_out
#define NBLK3 (HWn / HWPC)   // 576

typedef unsigned long long u64;
typedef unsigned int u32;

// Scratch (no runtime allocation allowed)
__device__ float g_partial[Bn * NBLK1 * Dn * Dn];  // per-block energy partials
__device__ float g_attn[Bn * Dn * Dn];             // gamma * softmax(energy), [b][d][e]

// ---- fp16 split helpers ----
__device__ __forceinline__ u32 packhf2(float f0, float f1) {
    u32 r; asm("cvt.rn.f16x2.f32 %0, %1, %2;" : "=r"(r) : "f"(f1), "f"(f0)); return r;
}
__device__ __forceinline__ float hflo(u32 p) {
    return __half2float(__ushort_as_half((unsigned short)(p & 0xffffu)));
}
__device__ __forceinline__ float hfhi(u32 p) {
    return __half2float(__ushort_as_half((unsigned short)(p >> 16)));
}

// ---- ldmatrix / mma wrappers ----
__device__ __forceinline__ void ldsm_x4(u32* r, u32 addr) {
    asm volatile("ldmatrix.sync.aligned.m8n8.x4.shared.b16 {%0,%1,%2,%3}, [%4];"
        : "=r"(r[0]), "=r"(r[1]), "=r"(r[2]), "=r"(r[3]) : "r"(addr));
}
__device__ __forceinline__ void ldsm_x4t(u32* r, u32 addr) {
    asm volatile("ldmatrix.sync.aligned.m8n8.x4.trans.shared.b16 {%0,%1,%2,%3}, [%4];"
        : "=r"(r[0]), "=r"(r[1]), "=r"(r[2]), "=r"(r[3]) : "r"(addr));
}
__device__ __forceinline__ void ldsm_x2(u32* r, u32 addr) {
    asm volatile("ldmatrix.sync.aligned.m8n8.x2.shared.b16 {%0,%1}, [%2];"
        : "=r"(r[0]), "=r"(r[1]) : "r"(addr));
}
__device__ __forceinline__ void ldsm_x2t(u32* r, u32 addr) {
    asm volatile("ldmatrix.sync.aligned.m8n8.x2.trans.shared.b16 {%0,%1}, [%2];"
        : "=r"(r[0]), "=r"(r[1]) : "r"(addr));
}
__device__ __forceinline__ void mma_hf(float* d, const u32* a, const u32* b) {
    asm volatile("mma.sync.aligned.m16n8k16.row.col.f32.f16.f16.f32 "
        "{%0,%1,%2,%3}, {%4,%5,%6,%7}, {%8,%9}, {%0,%1,%2,%3};"
        : "+f"(d[0]), "+f"(d[1]), "+f"(d[2]), "+f"(d[3])
        : "r"(a[0]), "r"(a[1]), "r"(a[2]), "r"(a[3]), "r"(b[0]), "r"(b[1]));
}

// ============================================================================
// Kernel 1: fused q/k projection + energy, split-fp16 MMA (3-MMA, precision-
// critical). Unchanged from the 602us passing version.
// ============================================================================

#define E_WQH 0                       // Wq hi [16][72]
#define E_WQL 1152
#define E_WKH 2304
#define E_WKL 3456
#define E_XH  4608                    // X  hi [64 c][104 d]
#define E_XL  11264
#define E_QH  17920                   // q hi [16 o][104 d]
#define E_QL  19584
#define E_KH  21248                   // k hi [16 o][104 e]
#define E_KL  22912
#define E_TOT 24576                   // *2 = 49152 bytes

__global__ void __launch_bounds__(256, 2) k_energy(
    const float* __restrict__ x, const float* __restrict__ Wq,
    const float* __restrict__ bq, const float* __restrict__ Wk,
    const float* __restrict__ bk)
{
    extern __shared__ __align__(16) u32 smw[];
    __half* smh = reinterpret_cast<__half*>(smw);
    const u32 sb = (u32)__cvta_generic_to_shared(smw);

    const int b = blockIdx.y, g = blockIdx.x, t = threadIdx.x;
    const int w = t >> 5, l = t & 31;

    // one-time: split Wq, Wk into hi/lo fp16
    for (int i = t; i < CQn * Cn; i += 256) {
        int o = i >> 6, c = i & 63;
        float vq = Wq[i], vk = Wk[i];
        __half hq = __float2half_rn(vq), hk = __float2half_rn(vk);
        smh[E_WQH + o * 72 + c] = hq;
        smh[E_WQL + o * 72 + c] = __float2half_rn(vq - __half2float(hq));
        smh[E_WKH + o * 72 + c] = hk;
        smh[E_WKL + o * 72 + c] = __float2half_rn(vk - __half2float(hk));
    }

    const int qk  = w >> 2;
    const int nb  = (w & 3) * 3;
    const int gid = l >> 2, tig = l & 3;
    const int waH = qk ? E_WKH : E_WQH;
    const int waL = qk ? E_WKL : E_WQL;
    const int tH  = qk ? E_KH : E_QH;
    const int tL  = qk ? E_KL : E_QL;
    const float* bias = qk ? bk : bq;
    const float bs0 = bias[gid], bs1 = bias[gid + 8];

    // lane-constant ldmatrix address parts
    const int arow  = (l & 7) + (l & 8);          // A non-trans: m-row 0..15
    const int acol8 = ((l >> 4) & 1) * 8;         // A non-trans: k-half
    const int xrow  = (l & 15);                   // B trans: k-row 0..15
    const int pl    = (l >> 4) & 1;               // pair-tile select (x4)
    // A trans (energy): k-row and m-col halves
    const int atrow = (l & 7) + ((l >> 4) & 1) * 8;
    const int amcol = ((l >> 3) & 1) * 8;

    const int mw = w >> 2, nwq = w & 3;

    float E[3][3][4];
    #pragma unroll
    for (int im = 0; im < 3; im++)
        #pragma unroll
        for (int in = 0; in < 3; in++)
            #pragma unroll
            for (int p = 0; p < 4; p++) E[im][in][p] = 0.f;

    const int cp = t >> 2;
    const int d0 = (t & 3) * 24;
    const float* xb = x + (size_t)b * Cn * HWn * Dn;

    // prefetch X column 0
    float4 xf[6];
    {
        const float4* src = reinterpret_cast<const float4*>(
            xb + ((size_t)cp * HWn + (size_t)g * HWPB1) * Dn + d0);
        #pragma unroll
        for (int j = 0; j < 6; j++) xf[j] = src[j];
    }

    __syncthreads();

    for (int it = 0; it < HWPB1; ++it) {
        // ---- stage X: split hi/lo fp16, merged 128-bit stores ----
        #pragma unroll
        for (int jp = 0; jp < 3; jp++) {
            float4 fa = xf[2 * jp], fb = xf[2 * jp + 1];
            int e0 = cp * 104 + d0 + 8 * jp;
            u32 h0 = packhf2(fa.x, fa.y), h1 = packhf2(fa.z, fa.w);
            u32 h2 = packhf2(fb.x, fb.y), h3 = packhf2(fb.z, fb.w);
            u32 l0 = packhf2(fa.x - hflo(h0), fa.y - hfhi(h0));
            u32 l1 = packhf2(fa.z - hflo(h1), fa.w - hfhi(h1));
            u32 l2 = packhf2(fb.x - hflo(h2), fb.y - hfhi(h2));
            u32 l3 = packhf2(fb.z - hflo(h3), fb.w - hfhi(h3));
            *reinterpret_cast<uint4*>(&smh[E_XH + e0]) = make_uint4(h0, h1, h2, h3);
            *reinterpret_cast<uint4*>(&smh[E_XL + e0]) = make_uint4(l0, l1, l2, l3);
        }
        __syncthreads();

        // issue next column's LDGs; consumed next iteration (hides DRAM lat)
        if (it + 1 < HWPB1) {
            const float4* src = reinterpret_cast<const float4*>(
                xb + ((size_t)cp * HWn + (size_t)(g * HWPB1 + it + 1)) * Dn + d0);
            #pragma unroll
            for (int j = 0; j < 6; j++) xf[j] = src[j];
        }

        // ---- projection: acc = W * X + bias (3 n-tiles; B x4-paired) ----
        float acc[3][4];
        #pragma unroll
        for (int nj = 0; nj < 3; nj++) {
            acc[nj][0] = bs0; acc[nj][1] = bs0; acc[nj][2] = bs1; acc[nj][3] = bs1;
        }
        #pragma unroll
        for (int ks = 0; ks < 4; ks++) {
            u32 ah[4], al[4];
            ldsm_x4(ah, sb + 2u * (waH + arow * 72 + acol8 + 16 * ks));
            ldsm_x4(al, sb + 2u * (waL + arow * 72 + acol8 + 16 * ks));
            u32 rh[4], rl[4];
            u32 beP = (16 * ks + xrow) * 104 + 8 * (nb + pl);
            ldsm_x4t(rh, sb + 2u * (E_XH + beP));
            ldsm_x4t(rl, sb + 2u * (E_XL + beP));
            mma_hf(acc[0], ah, rh);     mma_hf(acc[0], ah, rl);     mma_hf(acc[0], al, rh);
            mma_hf(acc[1], ah, rh + 2); mma_hf(acc[1], ah, rl + 2); mma_hf(acc[1], al, rh + 2);
            u32 bh2[2], bl2[2];
            u32 be2 = (16 * ks + xrow) * 104 + 8 * (nb + 2);
            ldsm_x2t(bh2, sb + 2u * (E_XH + be2));
            ldsm_x2t(bl2, sb + 2u * (E_XL + be2));
            mma_hf(acc[2], ah, bh2); mma_hf(acc[2], ah, bl2); mma_hf(acc[2], al, bh2);
        }

        // ---- write q/k NON-transposed [o][104 d], packed 32-bit stores ----
        #pragma unroll
        for (int nj = 0; nj < 3; nj++) {
            int dc = 8 * (nb + nj) + 2 * tig;
            u32 h01 = packhf2(acc[nj][0], acc[nj][1]);
            u32 l01 = packhf2(acc[nj][0] - hflo(h01), acc[nj][1] - hfhi(h01));
            u32 h23 = packhf2(acc[nj][2], acc[nj][3]);
            u32 l23 = packhf2(acc[nj][2] - hflo(h23), acc[nj][3] - hfhi(h23));
            int b0 = gid * 104 + dc;
            int b1 = (gid + 8) * 104 + dc;
            smw[(tH + b0) >> 1] = h01;
            smw[(tL + b0) >> 1] = l01;
            smw[(tH + b1) >> 1] = h23;
            smw[(tL + b1) >> 1] = l23;
        }
        __syncthreads();

        // ---- energy: E += q^T k  (A/B via ldmatrix.trans from [o][*]) ----
        u32 kh[3][2], kl[3][2];
        {
            u32 r4[4];
            u32 beP = xrow * 104 + 8 * (3 * nwq + pl);
            ldsm_x4t(r4, sb + 2u * (E_KH + beP));
            kh[0][0] = r4[0]; kh[0][1] = r4[1]; kh[1][0] = r4[2]; kh[1][1] = r4[3];
            ldsm_x4t(r4, sb + 2u * (E_KL + beP));
            kl[0][0] = r4[0]; kl[0][1] = r4[1]; kl[1][0] = r4[2]; kl[1][1] = r4[3];
            u32 be2 = xrow * 104 + 8 * (3 * nwq + 2);
            ldsm_x2t(kh[2], sb + 2u * (E_KH + be2));
            ldsm_x2t(kl[2], sb + 2u * (E_KL + be2));
        }
        #pragma unroll
        for (int im = 0; im < 3; im++) {
            u32 ah[4], al[4];
            u32 ae = atrow * 104 + 16 * (3 * mw + im) + amcol;
            ldsm_x4t(ah, sb + 2u * (E_QH + ae));
            ldsm_x4t(al, sb + 2u * (E_QL + ae));
            #pragma unroll
            for (int in = 0; in < 3; in++) {
                mma_hf(E[im][in], ah, kh[in]);
                mma_hf(E[im][in], ah, kl[in]);
                mma_hf(E[im][in], al, kh[in]);
            }
        }
        // next X-store touches only XH/XL (disjoint from q/k); the sync after
        // it orders energy reads against the next projection's q/k writes.
    }

    float* dst = g_partial + ((size_t)(b * NBLK1 + g)) * Dn * Dn;
    #pragma unroll
    for (int im = 0; im < 3; im++)
        #pragma unroll
        for (int in = 0; in < 3; in++) {
            int r = 16 * (3 * mw + im) + gid;
            int c = 8 * (3 * nwq + in) + 2 * tig;
            *reinterpret_cast<float2*>(&dst[(size_t)r * Dn + c]) =
                make_float2(E[im][in][0], E[im][in][1]);
            *reinterpret_cast<float2*>(&dst[(size_t)(r + 8) * Dn + c]) =
                make_float2(E[im][in][2], E[im][in][3]);
        }
}

// ============================================================================
// Kernel 2: reduce partials, softmax over e, fold gamma. Stores [b][d][e].
// ============================================================================
__global__ void k_softmax(const float* __restrict__ gamma) {
    const int b = blockIdx.y, d = blockIdx.x;
    const int e = threadIdx.x;
    float v = 0.f;
    for (int g = 0; g < NBLK1; g++)
        v += g_partial[(((size_t)b * NBLK1 + g) * Dn + d) * Dn + e];
    __shared__ float sv[Dn];
    __shared__ float red;
    sv[e] = v;
    __syncthreads();
    if (e == 0) { float m = sv[0]; for (int i = 1; i < Dn; i++) m = fmaxf(m, sv[i]); red = m; }
    __syncthreads();
    float pe = expf(v - red);
    sv[e] = pe;
    __syncthreads();
    if (e == 0) { float s = 0.f; for (int i = 0; i < Dn; i++) s += sv[i]; red = s; }
    __syncthreads();
    g_attn[((size_t)b * Dn + d) * Dn + e] = gamma[0] * pe / red;
}

// ============================================================================
// Kernel 3: fused V projection + attention apply + residual — now fp16.
//   GEMM-A: Wv split-fp16 x X-hi only: 2 MMAs (dropped Wv*xl ~2^-11)
//   GEMM-B: V split-fp16 x A' SINGLE-fp16: 2 MMAs (A'-lo removed)
//   Residual: X hi+lo reconstruction (exact to 2^-21).
// MMAs 180->120, ldmatrix 80->50 per warp/hw; smem 111.6->91.6 KB.
// ============================================================================
#define S_WVH 0                       // Wv hi [64][72]
#define S_WVL 4608
#define S_XH  9216                    // X hi [64][104]
#define S_XL  15872                   // X lo (residual exactness; GEMM uses hi)
#define S_VH  22528                   // V hi [64][104]
#define S_VL  29184
#define S_AH  35840                   // A' single fp16 [96][104]
#define S_TOT 45824                   // *2 = 91648 bytes

__global__ void __launch_bounds__(256, 2) k_out(
    const float* __restrict__ x, const float* __restrict__ Wv,
    const float* __restrict__ bv, float* __restrict__ out)
{
    extern __shared__ __align__(16) u32 smw[];
    __half* smh = reinterpret_cast<__half*>(smw);
    const u32 sb = (u32)__cvta_generic_to_shared(smw);

    const int b = blockIdx.y, g = blockIdx.x, t = threadIdx.x;
    const int w = t >> 5, l = t & 31;

    // one-time: split Wv (fp16 hi/lo); A' single fp16
    for (int i = t; i < Cn * Cn; i += 256) {
        int c = i >> 6, cc = i & 63;
        float v = Wv[i];
        __half h = __float2half_rn(v);
        smh[S_WVH + c * 72 + cc] = h;
        smh[S_WVL + c * 72 + cc] = __float2half_rn(v - __half2float(h));
    }
    const float* Ab = g_attn + (size_t)b * Dn * Dn;
    for (int i = t; i < Dn * Dn; i += 256) {
        int d = i / 96, e = i % 96;
        smh[S_AH + d * 104 + e] = __float2half_rn(Ab[i]);
    }

    const int mi = w & 3, nj0 = (w >> 2) * 6;
    const int gid = l >> 2, tig = l & 3;
    const float bv0 = bv[16 * mi + gid], bv1 = bv[16 * mi + gid + 8];

    const int arow  = (l & 7) + (l & 8);
    const int acol8 = ((l >> 4) & 1) * 8;
    const int eWa = (16 * mi + arow) * 72 + acol8;
    const int eVa = (16 * mi + arow) * 104 + acol8;
    const int xrow = (l & 15);
    const int pl   = (l >> 4) & 1;
    const int prow = (l & 7);
    const int pcol8 = ((l >> 3) & 1) * 8;

    const int cp = t >> 2;
    const int d0 = (t & 3) * 24;

    const float* xb = x   + (size_t)b * Cn * HWn * Dn;
    float*       ob = out + (size_t)b * Cn * HWn * Dn;

    // prefetch X column 0
    float4 xf[6];
    {
        const float4* src = reinterpret_cast<const float4*>(
            xb + ((size_t)cp * HWn + (size_t)g * HWPC) * Dn + d0);
        #pragma unroll
        for (int j = 0; j < 6; j++) xf[j] = src[j];
    }

    __syncthreads();

    for (int it = 0; it < HWPC; ++it) {
        const int hw = g * HWPC + it;

        // ---- stage X: split hi/lo fp16, merged 128-bit stores ----
        #pragma unroll
        for (int jp = 0; jp < 3; jp++) {
            float4 fa = xf[2 * jp], fb = xf[2 * jp + 1];
            int e0 = cp * 104 + d0 + 8 * jp;
            u32 h0 = packhf2(fa.x, fa.y), h1 = packhf2(fa.z, fa.w);
            u32 h2 = packhf2(fb.x, fb.y), h3 = packhf2(fb.z, fb.w);
            u32 l0 = packhf2(fa.x - hflo(h0), fa.y - hfhi(h0));
            u32 l1 = packhf2(fa.z - hflo(h1), fa.w - hfhi(h1));
            u32 l2 = packhf2(fb.x - hflo(h2), fb.y - hfhi(h2));
            u32 l3 = packhf2(fb.z - hflo(h3), fb.w - hfhi(h3));
            *reinterpret_cast<uint4*>(&smh[S_XH + e0]) = make_uint4(h0, h1, h2, h3);
            *reinterpret_cast<uint4*>(&smh[S_XL + e0]) = make_uint4(l0, l1, l2, l3);
        }
        __syncthreads();

        if (it + 1 < HWPC) {
            const float4* src = reinterpret_cast<const float4*>(
                xb + ((size_t)cp * HWn + (size_t)(hw + 1)) * Dn + d0);
            #pragma unroll
            for (int j = 0; j < 6; j++) xf[j] = src[j];
        }

        // ---- GEMM-A: acc = Wv * X + bv (X-hi only; 2 MMAs per pair) ----
        float acc[6][4];
        #pragma unroll
        for (int nj = 0; nj < 6; nj++) {
            acc[nj][0] = bv0; acc[nj][1] = bv0; acc[nj][2] = bv1; acc[nj][3] = bv1;
        }
        #pragma unroll
        for (int ks = 0; ks < 4; ks++) {
            u32 wh[4], wl[4];
            ldsm_x4(wh, sb + 2u * (S_WVH + eWa + 16 * ks));
            ldsm_x4(wl, sb + 2u * (S_WVL + eWa + 16 * ks));
            #pragma unroll
            for (int njp = 0; njp < 6; njp += 2) {
                u32 rh[4];
                u32 beP = (16 * ks + xrow) * 104 + 8 * (nj0 + njp + pl);
                ldsm_x4t(rh, sb + 2u * (S_XH + beP));
                mma_hf(acc[njp],     wh, rh);     mma_hf(acc[njp],     wl, rh);
                mma_hf(acc[njp + 1], wh, rh + 2); mma_hf(acc[njp + 1], wl, rh + 2);
            }
        }

        // ---- split V (fp16 hi/lo) to SMEM ----
        #pragma unroll
        for (int nj = 0; nj < 6; nj++) {
            int e  = 8 * (nj0 + nj) + 2 * tig;
            int r0 = 16 * mi + gid, r1 = r0 + 8;
            u32 h0 = packhf2(acc[nj][0], acc[nj][1]);
            u32 p0 = packhf2(acc[nj][0] - hflo(h0), acc[nj][1] - hfhi(h0));
            u32 h1 = packhf2(acc[nj][2], acc[nj][3]);
            u32 p1 = packhf2(acc[nj][2] - hflo(h1), acc[nj][3] - hfhi(h1));
            smw[(S_VH + r0 * 104 + e) >> 1] = h0;
            smw[(S_VL + r0 * 104 + e) >> 1] = p0;
            smw[(S_VH + r1 * 104 + e) >> 1] = h1;
            smw[(S_VL + r1 * 104 + e) >> 1] = p1;
        }
        __syncthreads();

        // ---- GEMM-B: acc = V * A'^T (A' single; 2 MMAs per pair) ----
        #pragma unroll
        for (int nj = 0; nj < 6; nj++) {
            acc[nj][0] = 0.f; acc[nj][1] = 0.f; acc[nj][2] = 0.f; acc[nj][3] = 0.f;
        }
        #pragma unroll
        for (int ks = 0; ks < 6; ks++) {
            u32 vh[4], vl[4];
            ldsm_x4(vh, sb + 2u * (S_VH + eVa + 16 * ks));
            ldsm_x4(vl, sb + 2u * (S_VL + eVa + 16 * ks));
            #pragma unroll
            for (int njp = 0; njp < 6; njp += 2) {
                u32 ra[4];
                u32 beP = (8 * (nj0 + njp + pl) + prow) * 104 + 16 * ks + pcol8;
                ldsm_x4(ra, sb + 2u * (S_AH + beP));
                mma_hf(acc[njp],     vh, ra);     mma_hf(acc[njp],     vl, ra);
                mma_hf(acc[njp + 1], vh, ra + 2); mma_hf(acc[njp + 1], vl, ra + 2);
            }
        }

        // ---- residual (X = hi + lo, exact) + store ----
        #pragma unroll
        for (int nj = 0; nj < 6; nj++) {
            int d  = 8 * (nj0 + nj) + 2 * tig;
            int r0 = 16 * mi + gid, r1 = r0 + 8;
            u32 xh0 = smw[(S_XH + r0 * 104 + d) >> 1], xl0 = smw[(S_XL + r0 * 104 + d) >> 1];
            u32 xh1 = smw[(S_XH + r1 * 104 + d) >> 1], xl1 = smw[(S_XL + r1 * 104 + d) >> 1];
            float2 o0, o1;
            o0.x = acc[nj][0] + hflo(xh0) + hflo(xl0);
            o0.y = acc[nj][1] + hfhi(xh0) + hfhi(xl0);
            o1.x = acc[nj][2] + hflo(xh1) + hflo(xl1);
            o1.y = acc[nj][3] + hfhi(xh1) + hfhi(xl1);
            *reinterpret_cast<float2*>(ob + ((size_t)r0 * HWn + hw) * Dn + d) = o0;
            *reinterpret_cast<float2*>(ob + ((size_t)r1 * HWn + hw) * Dn + d) = o1;
        }
        __syncthreads();
    }
}

extern "C" void kernel_launch(void* const* d_in, const int* in_sizes, int n_in,
                              void* d_out, int out_size) {
    (void)in_sizes; (void)n_in; (void)out_size;
    const float* x     = (const float*)d_in[0];
    const float* Wq    = (const float*)d_in[1];
    const float* bq    = (const float*)d_in[2];
    const float* Wk    = (const float*)d_in[3];
    const float* bk    = (const float*)d_in[4];
    const float* Wv    = (const float*)d_in[5];
    const float* bv    = (const float*)d_in[6];
    const float* gamma = (const float*)d_in[7];
    float* out = (float*)d_out;

    cudaFuncSetAttribute(k_energy, cudaFuncAttributeMaxDynamicSharedMemorySize, E_TOT * 2);
    cudaFuncSetAttribute(k_out,    cudaFuncAttributeMaxDynamicSharedMemorySize, S_TOT * 2);

    k_energy<<<dim3(NBLK1, Bn), 256, E_TOT * 2>>>(x, Wq, bq, Wk, bk);
    k_softmax<<<dim3(Dn, Bn), Dn>>>(gamma);
    k_out<<<dim3(NBLK3, Bn), 256, S_TOT * 2>>>(x, Wv, bv, out);
}